// round 1
// baseline (speedup 1.0000x reference)
#include <cuda_runtime.h>

#define NN 50000
#define EE 600000
#define DEPTH 8

// ---------------- scratch (alloc-free rule: __device__ globals) ----------------
__device__ __align__(16) float g_t1[NN * 256];
__device__ __align__(16) float g_t2[NN * 256];
__device__ __align__(16) float g_y [NN * 128];
__device__ __align__(16) float g_s [NN * 128];

// ---------------- fused GEMM: C[N,M] = leakyrelu(A[N,K] @ W[K,M] + b) ----------
// BM=BN=128, BK=8, 256 threads, 8x8 per-thread tile.
__global__ __launch_bounds__(256, 2)
void sgemm_bias_lrelu(const float* __restrict__ A, const float* __restrict__ W,
                      const float* __restrict__ bias, float* __restrict__ C,
                      int N, int K, int M)
{
    __shared__ float As[8][132];
    __shared__ float Bs[8][132];

    const int tid = threadIdx.x;
    const int bm = blockIdx.y * 128;
    const int bn = blockIdx.x * 128;

    // A-tile load mapping: one float4 per thread (128 rows x 8 k)
    const int a_row = tid >> 1;          // 0..127
    const int a_col = (tid & 1) << 2;    // 0 or 4
    // B-tile load mapping: one float4 per thread (8 k x 128 cols)
    const int b_row = tid >> 5;          // 0..7
    const int b_col = (tid & 31) << 2;   // 0..124

    const int tx = tid & 15;             // col group (8 cols each)
    const int ty = tid >> 4;             // row group (8 rows each)

    float acc[8][8];
#pragma unroll
    for (int i = 0; i < 8; i++)
#pragma unroll
        for (int j = 0; j < 8; j++) acc[i][j] = 0.f;

    for (int k0 = 0; k0 < K; k0 += 8) {
        // load A tile (transposed into smem), guard rows
        float4 av;
        const int gr = bm + a_row;
        if (gr < N) av = *(const float4*)(A + (size_t)gr * K + k0 + a_col);
        else        av = make_float4(0.f, 0.f, 0.f, 0.f);
        As[a_col + 0][a_row] = av.x;
        As[a_col + 1][a_row] = av.y;
        As[a_col + 2][a_row] = av.z;
        As[a_col + 3][a_row] = av.w;

        // load B tile (K and M are always multiples of 8/128 here)
        float4 bv = *(const float4*)(W + (size_t)(k0 + b_row) * M + bn + b_col);
        *(float4*)&Bs[b_row][b_col] = bv;

        __syncthreads();

#pragma unroll
        for (int k = 0; k < 8; k++) {
            float a[8], b[8];
            *(float4*)&a[0] = *(const float4*)&As[k][ty * 8];
            *(float4*)&a[4] = *(const float4*)&As[k][ty * 8 + 4];
            *(float4*)&b[0] = *(const float4*)&Bs[k][tx * 8];
            *(float4*)&b[4] = *(const float4*)&Bs[k][tx * 8 + 4];
#pragma unroll
            for (int i = 0; i < 8; i++)
#pragma unroll
                for (int j = 0; j < 8; j++)
                    acc[i][j] += a[i] * b[j];
        }
        __syncthreads();
    }

    // epilogue: bias + leaky-relu (slope 0.01), float4 stores
#pragma unroll
    for (int i = 0; i < 8; i++) {
        const int gr = bm + ty * 8 + i;
        if (gr >= N) continue;
#pragma unroll
        for (int j = 0; j < 8; j += 4) {
            const int gc = bn + tx * 8 + j;
            float4 v;
            v.x = acc[i][j + 0] + bias[gc + 0];
            v.y = acc[i][j + 1] + bias[gc + 1];
            v.z = acc[i][j + 2] + bias[gc + 2];
            v.w = acc[i][j + 3] + bias[gc + 3];
            v.x = v.x >= 0.f ? v.x : 0.01f * v.x;
            v.y = v.y >= 0.f ? v.y : 0.01f * v.y;
            v.z = v.z >= 0.f ? v.z : 0.01f * v.z;
            v.w = v.w >= 0.f ? v.w : 0.01f * v.w;
            *(float4*)(C + (size_t)gr * M + gc) = v;
        }
    }
}

// ---------------- zero ----------------
__global__ void zero_kernel(float* __restrict__ p, int n)
{
    int i = blockIdx.x * blockDim.x + threadIdx.x;
    if (i < n) p[i] = 0.f;
}

// ---------------- scatter: s[src[e]] += val[e] * y[dst[e]] ----------------
// one thread per (edge, dim); 4 warps per edge, coalesced 128B per warp
__global__ void scatter_kernel(const int* __restrict__ src, const int* __restrict__ dst,
                               const float* __restrict__ vals,
                               const float* __restrict__ y, float* __restrict__ out,
                               int E)
{
    int gid = blockIdx.x * blockDim.x + threadIdx.x;
    int e = gid >> 7;
    int d = gid & 127;
    if (e >= E) return;
    float v = vals[e];
    int s = src[e];
    int t = dst[e];
    atomicAdd(&out[(size_t)s * 128 + d], v * y[(size_t)t * 128 + d]);
}

// ---------------- residual: x += mask[node] * y ----------------
__global__ void residual_kernel(float* __restrict__ x, const float* __restrict__ y,
                                const float* __restrict__ mask, int n)
{
    int i = blockIdx.x * blockDim.x + threadIdx.x;
    if (i < n) x[i] += mask[i >> 7] * y[i];
}

// ---------------- host orchestration ----------------
static inline void launch_gemm(const float* A, const float* W, const float* b,
                               float* C, int N, int K, int M)
{
    dim3 grid(M / 128, (N + 127) / 128);
    sgemm_bias_lrelu<<<grid, 256>>>(A, W, b, C, N, K, M);
}

extern "C" void kernel_launch(void* const* d_in, const int* in_sizes, int n_in,
                              void* d_out, int out_size)
{
    const float* node_inputs = (const float*)d_in[0];
    const int*   edge_src    = (const int*)  d_in[1];
    const int*   edge_dst    = (const int*)  d_in[2];
    const float* adj_vals    = (const float*)d_in[3];
    const float* masks       = (const float*)d_in[4];
    const float* W_h1 = (const float*)d_in[5];
    const float* b_h1 = (const float*)d_in[6];
    const float* W_h2 = (const float*)d_in[7];
    const float* b_h2 = (const float*)d_in[8];
    const float* W_h3 = (const float*)d_in[9];
    const float* b_h3 = (const float*)d_in[10];
    const float* W_f1 = (const float*)d_in[11];
    const float* b_f1 = (const float*)d_in[12];
    const float* W_f2 = (const float*)d_in[13];
    const float* b_f2 = (const float*)d_in[14];
    const float* W_f3 = (const float*)d_in[15];
    const float* b_f3 = (const float*)d_in[16];

    float* x = (float*)d_out;   // x lives in d_out

    float *t1, *t2, *y, *s;
    cudaGetSymbolAddress((void**)&t1, g_t1);
    cudaGetSymbolAddress((void**)&t2, g_t2);
    cudaGetSymbolAddress((void**)&y,  g_y);
    cudaGetSymbolAddress((void**)&s,  g_s);

    const int NE = NN * 128;  // 6.4M elements

    // embedding MLP: x = mlp3(node_inputs; W_h*)
    launch_gemm(node_inputs, W_h1, b_h1, t1, NN, 128, 256);
    launch_gemm(t1,          W_h2, b_h2, t2, NN, 256, 256);
    launch_gemm(t2,          W_h3, b_h3, x,  NN, 256, 128);

    for (int d = 0; d < DEPTH; d++) {
        // y = mlp3(x; W_f*)
        launch_gemm(x,  W_f1, b_f1, t1, NN, 128, 256);
        launch_gemm(t1, W_f2, b_f2, t2, NN, 256, 256);
        launch_gemm(t2, W_f3, b_f3, y,  NN, 256, 128);

        // s = segment_sum(adj_vals * y[dst], src)
        zero_kernel<<<(NE + 255) / 256, 256>>>(s, NE);
        {
            long long tot = (long long)EE * 128;
            int blocks = (int)((tot + 255) / 256);
            scatter_kernel<<<blocks, 256>>>(edge_src + (size_t)d * EE,
                                            edge_dst + (size_t)d * EE,
                                            adj_vals + (size_t)d * EE,
                                            y, s, EE);
        }

        // y = mlp3(s; W_f*)
        launch_gemm(s,  W_f1, b_f1, t1, NN, 128, 256);
        launch_gemm(t1, W_f2, b_f2, t2, NN, 256, 256);
        launch_gemm(t2, W_f3, b_f3, y,  NN, 256, 128);

        // x += mask[d] * y
        residual_kernel<<<(NE + 255) / 256, 256>>>(x, y, masks + (size_t)d * NN, NE);
    }
}

// round 3
// speedup vs baseline: 1.6279x; 1.6279x over previous
#include <cuda_runtime.h>
#include <cuda_bf16.h>
#include <cstdint>

#define NN 50000
#define EE 600000
#define DEPTH 8

// ---------------- scratch (alloc-free rule: __device__ globals) ----------------
__device__ __align__(16) float g_t1[NN * 256];
__device__ __align__(16) float g_t2[NN * 256];
__device__ __align__(16) float g_y [NN * 128];
__device__ __align__(16) float g_s [NN * 128];
// transposed + bf16-split weights: [M][K] layout, 6 matrices packed
__device__ __align__(16) __nv_bfloat16 g_wt_hi[262144];
__device__ __align__(16) __nv_bfloat16 g_wt_lo[262144];

// ---------------- helpers ----------------
__device__ __forceinline__ uint32_t smem_to_u32(const void* smem_ptr) {
    uint32_t addr;
    asm("{ .reg .u64 tmp; cvta.to.shared.u64 tmp, %1; cvt.u32.u64 %0, tmp; }"
        : "=r"(addr) : "l"(smem_ptr));
    return addr;
}

__device__ __forceinline__ void ldmx4(uint32_t* d, uint32_t addr) {
    asm volatile("ldmatrix.sync.aligned.m8n8.x4.shared.b16 {%0,%1,%2,%3}, [%4];"
                 : "=r"(d[0]), "=r"(d[1]), "=r"(d[2]), "=r"(d[3]) : "r"(addr));
}

__device__ __forceinline__ void mma16816(float* c, const uint32_t* a, const uint32_t* b) {
    asm volatile(
        "mma.sync.aligned.m16n8k16.row.col.f32.bf16.bf16.f32 "
        "{%0,%1,%2,%3},{%4,%5,%6,%7},{%8,%9},{%0,%1,%2,%3};"
        : "+f"(c[0]), "+f"(c[1]), "+f"(c[2]), "+f"(c[3])
        : "r"(a[0]), "r"(a[1]), "r"(a[2]), "r"(a[3]), "r"(b[0]), "r"(b[1]));
}

// swizzled byte offset within a 128x32 bf16 tile (row stride 64B, 16B groups XORed)
__device__ __forceinline__ uint32_t swz(int row, int c16) {
    return (uint32_t)(row * 64) + (uint32_t)(((c16 ^ ((row >> 1) & 3)) << 4));
}

// ---------------- mma.sync GEMM: C[Nr,M] = lrelu(A[Nr,K] @ W[K,M] + b) ----------
// A fp32 (split in-kernel to bf16 hi/lo); W pre-transposed/split bf16 [M][K].
// 128x128 CTA tile, BK=32, double-buffered smem, 8 warps of 64x32.
__global__ __launch_bounds__(256, 1)
void gemm_mma(const float* __restrict__ A, const __nv_bfloat16* __restrict__ Bh,
              const __nv_bfloat16* __restrict__ Bl, const float* __restrict__ bias,
              float* __restrict__ C, int Nrows, int K, int M)
{
    extern __shared__ char smem[];   // 2 stages x 32KB: [Ah 8K][Al 8K][Bh 8K][Bl 8K]
    const uint32_t sbase = smem_to_u32(smem);

    const int tid = threadIdx.x;
    const int wid = tid >> 5;
    const int lid = tid & 31;
    const int bm = blockIdx.y * 128;
    const int bn = blockIdx.x * 128;
    const int mo = (wid >> 2) * 64;       // warp m offset (0/64)
    const int no = (wid & 3) * 32;        // warp n offset (0/32/64/96)

    const int nchunks = K >> 5;

    float acc[4][4][4];
#pragma unroll
    for (int i = 0; i < 4; i++)
#pragma unroll
        for (int j = 0; j < 4; j++)
#pragma unroll
            for (int q = 0; q < 4; q++) acc[i][j][q] = 0.f;

    // per-thread staging indices
    const int ar = tid >> 3;              // A stage row base (it*32 stride added)
    const int ac4 = (tid & 7) << 2;       // A float col
    const int c16A = ac4 >> 3;
    const int subA = ((ac4 >> 2) & 1) << 3;

    float4 stA[4];
    uint4  stB[4];

    // ---- prologue: load chunk 0 directly to stage 0 ----
    {
#pragma unroll
        for (int it = 0; it < 4; ++it) {
            const int r = ar + it * 32;
            const int grow = bm + r;
            stA[it] = (grow < Nrows) ? *(const float4*)(A + (size_t)grow * K + ac4)
                                     : make_float4(0.f, 0.f, 0.f, 0.f);
        }
#pragma unroll
        for (int it = 0; it < 4; ++it) {
            const int idx = it * 256 + tid;
            const int arr = idx >> 9;
            const int w = idx & 511;
            const int r = w >> 2, cc = w & 3;
            const __nv_bfloat16* src = (arr ? Bl : Bh) + (size_t)(bn + r) * K + (cc << 3);
            stB[it] = *(const uint4*)src;
        }
        char* dAh = smem;
        char* dAl = smem + 8192;
        char* dBh = smem + 16384;
        char* dBl = smem + 24576;
#pragma unroll
        for (int it = 0; it < 4; ++it) {
            const int r = ar + it * 32;
            const float4 v = stA[it];
            __nv_bfloat16 h0 = __float2bfloat16(v.x), h1 = __float2bfloat16(v.y);
            __nv_bfloat16 h2 = __float2bfloat16(v.z), h3 = __float2bfloat16(v.w);
            __nv_bfloat16 l0 = __float2bfloat16(v.x - __bfloat162float(h0));
            __nv_bfloat16 l1 = __float2bfloat16(v.y - __bfloat162float(h1));
            __nv_bfloat16 l2 = __float2bfloat16(v.z - __bfloat162float(h2));
            __nv_bfloat16 l3 = __float2bfloat16(v.w - __bfloat162float(h3));
            uint2 hp = make_uint2((uint32_t)__bfloat16_as_ushort(h0) | ((uint32_t)__bfloat16_as_ushort(h1) << 16),
                                  (uint32_t)__bfloat16_as_ushort(h2) | ((uint32_t)__bfloat16_as_ushort(h3) << 16));
            uint2 lp = make_uint2((uint32_t)__bfloat16_as_ushort(l0) | ((uint32_t)__bfloat16_as_ushort(l1) << 16),
                                  (uint32_t)__bfloat16_as_ushort(l2) | ((uint32_t)__bfloat16_as_ushort(l3) << 16));
            const uint32_t off = swz(r, c16A) + subA;
            *(uint2*)(dAh + off) = hp;
            *(uint2*)(dAl + off) = lp;
        }
#pragma unroll
        for (int it = 0; it < 4; ++it) {
            const int idx = it * 256 + tid;
            const int arr = idx >> 9;
            const int w = idx & 511;
            const int r = w >> 2, cc = w & 3;
            *(uint4*)((arr ? dBl : dBh) + swz(r, cc)) = stB[it];
        }
        __syncthreads();
    }

    for (int c = 0; c < nchunks; ++c) {
        const int stg = c & 1;
        const bool has_next = (c + 1 < nchunks);

        // issue next chunk's global loads (latency overlaps MMA below)
        if (has_next) {
            const int k0n = (c + 1) << 5;
#pragma unroll
            for (int it = 0; it < 4; ++it) {
                const int r = ar + it * 32;
                const int grow = bm + r;
                stA[it] = (grow < Nrows)
                          ? *(const float4*)(A + (size_t)grow * K + k0n + ac4)
                          : make_float4(0.f, 0.f, 0.f, 0.f);
            }
#pragma unroll
            for (int it = 0; it < 4; ++it) {
                const int idx = it * 256 + tid;
                const int arr = idx >> 9;
                const int w = idx & 511;
                const int r = w >> 2, cc = w & 3;
                const __nv_bfloat16* src = (arr ? Bl : Bh) + (size_t)(bn + r) * K + k0n + (cc << 3);
                stB[it] = *(const uint4*)src;
            }
        }

        // ---- compute on stage stg ----
        {
            const uint32_t Ah = sbase + (uint32_t)stg * 32768u;
            const uint32_t Al = Ah + 8192u;
            const uint32_t Bh_ = Ah + 16384u;
            const uint32_t Bl_ = Ah + 24576u;
            const int lrow = lid & 15;
            const int lc = lid >> 4;

#pragma unroll
            for (int ks = 0; ks < 2; ++ks) {
                const int cA = (ks << 1) + lc;
                uint32_t afh[4][4], afl[4][4];
#pragma unroll
                for (int i = 0; i < 4; ++i) {
                    const int row = mo + i * 16 + lrow;
                    const uint32_t so = swz(row, cA);
                    ldmx4(afh[i], Ah + so);
                    ldmx4(afl[i], Al + so);
                }
                uint32_t bfh[4][2], bfl[4][2];
#pragma unroll
                for (int jj = 0; jj < 2; ++jj) {
                    const int row = no + jj * 16 + lrow;
                    const uint32_t so = swz(row, cA);
                    uint32_t r4[4];
                    ldmx4(r4, Bh_ + so);
                    bfh[jj * 2 + 0][0] = r4[0]; bfh[jj * 2 + 0][1] = r4[2];
                    bfh[jj * 2 + 1][0] = r4[1]; bfh[jj * 2 + 1][1] = r4[3];
                    ldmx4(r4, Bl_ + so);
                    bfl[jj * 2 + 0][0] = r4[0]; bfl[jj * 2 + 0][1] = r4[2];
                    bfl[jj * 2 + 1][0] = r4[1]; bfl[jj * 2 + 1][1] = r4[3];
                }
#pragma unroll
                for (int i = 0; i < 4; ++i)
#pragma unroll
                    for (int j = 0; j < 4; ++j) {
                        mma16816(acc[i][j], afh[i], bfh[j]);
                        mma16816(acc[i][j], afh[i], bfl[j]);
                        mma16816(acc[i][j], afl[i], bfh[j]);
                    }
            }
        }

        // ---- store staged next chunk into stage^1 ----
        if (has_next) {
            char* dAh = smem + (stg ^ 1) * 32768;
            char* dAl = dAh + 8192;
            char* dBh = dAh + 16384;
            char* dBl = dAh + 24576;
#pragma unroll
            for (int it = 0; it < 4; ++it) {
                const int r = ar + it * 32;
                const float4 v = stA[it];
                __nv_bfloat16 h0 = __float2bfloat16(v.x), h1 = __float2bfloat16(v.y);
                __nv_bfloat16 h2 = __float2bfloat16(v.z), h3 = __float2bfloat16(v.w);
                __nv_bfloat16 l0 = __float2bfloat16(v.x - __bfloat162float(h0));
                __nv_bfloat16 l1 = __float2bfloat16(v.y - __bfloat162float(h1));
                __nv_bfloat16 l2 = __float2bfloat16(v.z - __bfloat162float(h2));
                __nv_bfloat16 l3 = __float2bfloat16(v.w - __bfloat162float(h3));
                uint2 hp = make_uint2((uint32_t)__bfloat16_as_ushort(h0) | ((uint32_t)__bfloat16_as_ushort(h1) << 16),
                                      (uint32_t)__bfloat16_as_ushort(h2) | ((uint32_t)__bfloat16_as_ushort(h3) << 16));
                uint2 lp = make_uint2((uint32_t)__bfloat16_as_ushort(l0) | ((uint32_t)__bfloat16_as_ushort(l1) << 16),
                                      (uint32_t)__bfloat16_as_ushort(l2) | ((uint32_t)__bfloat16_as_ushort(l3) << 16));
                const uint32_t off = swz(r, c16A) + subA;
                *(uint2*)(dAh + off) = hp;
                *(uint2*)(dAl + off) = lp;
            }
#pragma unroll
            for (int it = 0; it < 4; ++it) {
                const int idx = it * 256 + tid;
                const int arr = idx >> 9;
                const int w = idx & 511;
                const int r = w >> 2, cc = w & 3;
                *(uint4*)((arr ? dBl : dBh) + swz(r, cc)) = stB[it];
            }
        }
        __syncthreads();
    }

    // ---- epilogue: bias + leaky-relu, fp32 stores ----
    const int g = lid >> 2;
    const int t2 = (lid & 3) << 1;
#pragma unroll
    for (int i = 0; i < 4; ++i) {
        const int row0 = bm + mo + i * 16 + g;
        const int row1 = row0 + 8;
#pragma unroll
        for (int j = 0; j < 4; ++j) {
            const int col = bn + no + j * 8 + t2;
            const float2 bv = *(const float2*)(bias + col);
            if (row0 < Nrows) {
                float2 o;
                o.x = acc[i][j][0] + bv.x;
                o.y = acc[i][j][1] + bv.y;
                o.x = o.x >= 0.f ? o.x : 0.01f * o.x;
                o.y = o.y >= 0.f ? o.y : 0.01f * o.y;
                *(float2*)(C + (size_t)row0 * M + col) = o;
            }
            if (row1 < Nrows) {
                float2 o;
                o.x = acc[i][j][2] + bv.x;
                o.y = acc[i][j][3] + bv.y;
                o.x = o.x >= 0.f ? o.x : 0.01f * o.x;
                o.y = o.y >= 0.f ? o.y : 0.01f * o.y;
                *(float2*)(C + (size_t)row1 * M + col) = o;
            }
        }
    }
}

// ---------------- weight prep: transpose + bf16 split ----------------
__global__ void prep_w(const float* __restrict__ W, __nv_bfloat16* __restrict__ hi,
                       __nv_bfloat16* __restrict__ lo, int K, int M)
{
    int idx = blockIdx.x * blockDim.x + threadIdx.x;
    if (idx >= K * M) return;
    int k = idx / M, m = idx - k * M;
    float v = W[idx];
    __nv_bfloat16 h = __float2bfloat16(v);
    hi[(size_t)m * K + k] = h;
    lo[(size_t)m * K + k] = __float2bfloat16(v - __bfloat162float(h));
}

// ---------------- zero / scatter / residual ----------------
__global__ void zero_kernel(float* __restrict__ p, int n)
{
    int i = blockIdx.x * blockDim.x + threadIdx.x;
    if (i < n) p[i] = 0.f;
}

__global__ void scatter_kernel(const int* __restrict__ src, const int* __restrict__ dst,
                               const float* __restrict__ vals,
                               const float* __restrict__ y, float* __restrict__ out,
                               int E)
{
    int gid = blockIdx.x * blockDim.x + threadIdx.x;
    int e = gid >> 7;
    int d = gid & 127;
    if (e >= E) return;
    float v = vals[e];
    int s = src[e];
    int t = dst[e];
    atomicAdd(&out[(size_t)s * 128 + d], v * y[(size_t)t * 128 + d]);
}

__global__ void residual_kernel(float* __restrict__ x, const float* __restrict__ y,
                                const float* __restrict__ mask, int n)
{
    int i = blockIdx.x * blockDim.x + threadIdx.x;
    if (i < n) x[i] += mask[i >> 7] * y[i];
}

// ---------------- host orchestration ----------------
static const int GEMM_SMEM = 65536;

static inline void launch_gemm(const float* A, const __nv_bfloat16* Bh,
                               const __nv_bfloat16* Bl, const float* bias,
                               float* C, int K, int M)
{
    dim3 grid(M / 128, (NN + 127) / 128);
    gemm_mma<<<grid, 256, GEMM_SMEM>>>(A, Bh, Bl, bias, C, NN, K, M);
}

extern "C" void kernel_launch(void* const* d_in, const int* in_sizes, int n_in,
                              void* d_out, int out_size)
{
    const float* node_inputs = (const float*)d_in[0];
    const int*   edge_src    = (const int*)  d_in[1];
    const int*   edge_dst    = (const int*)  d_in[2];
    const float* adj_vals    = (const float*)d_in[3];
    const float* masks       = (const float*)d_in[4];
    const float* W_h1 = (const float*)d_in[5];
    const float* b_h1 = (const float*)d_in[6];
    const float* W_h2 = (const float*)d_in[7];
    const float* b_h2 = (const float*)d_in[8];
    const float* W_h3 = (const float*)d_in[9];
    const float* b_h3 = (const float*)d_in[10];
    const float* W_f1 = (const float*)d_in[11];
    const float* b_f1 = (const float*)d_in[12];
    const float* W_f2 = (const float*)d_in[13];
    const float* b_f2 = (const float*)d_in[14];
    const float* W_f3 = (const float*)d_in[15];
    const float* b_f3 = (const float*)d_in[16];

    float* x = (float*)d_out;

    float *t1, *t2, *y, *s;
    __nv_bfloat16 *whi, *wlo;
    cudaGetSymbolAddress((void**)&t1,  g_t1);
    cudaGetSymbolAddress((void**)&t2,  g_t2);
    cudaGetSymbolAddress((void**)&y,   g_y);
    cudaGetSymbolAddress((void**)&s,   g_s);
    cudaGetSymbolAddress((void**)&whi, g_wt_hi);
    cudaGetSymbolAddress((void**)&wlo, g_wt_lo);

    cudaFuncSetAttribute(gemm_mma, cudaFuncAttributeMaxDynamicSharedMemorySize, GEMM_SMEM);

    // packed offsets for the 6 transposed/split weight matrices
    const int OH1 = 0, OH2 = 32768, OH3 = 98304, OF1 = 131072, OF2 = 163840, OF3 = 229376;

    prep_w<<<(128 * 256 + 255) / 256, 256>>>(W_h1, whi + OH1, wlo + OH1, 128, 256);
    prep_w<<<(256 * 256 + 255) / 256, 256>>>(W_h2, whi + OH2, wlo + OH2, 256, 256);
    prep_w<<<(256 * 128 + 255) / 256, 256>>>(W_h3, whi + OH3, wlo + OH3, 256, 128);
    prep_w<<<(128 * 256 + 255) / 256, 256>>>(W_f1, whi + OF1, wlo + OF1, 128, 256);
    prep_w<<<(256 * 256 + 255) / 256, 256>>>(W_f2, whi + OF2, wlo + OF2, 256, 256);
    prep_w<<<(256 * 128 + 255) / 256, 256>>>(W_f3, whi + OF3, wlo + OF3, 256, 128);

    const int NE = NN * 128;

    // embedding MLP
    launch_gemm(node_inputs, whi + OH1, wlo + OH1, b_h1, t1, 128, 256);
    launch_gemm(t1,          whi + OH2, wlo + OH2, b_h2, t2, 256, 256);
    launch_gemm(t2,          whi + OH3, wlo + OH3, b_h3, x,  256, 128);

    for (int d = 0; d < DEPTH; d++) {
        launch_gemm(x,  whi + OF1, wlo + OF1, b_f1, t1, 128, 256);
        launch_gemm(t1, whi + OF2, wlo + OF2, b_f2, t2, 256, 256);
        launch_gemm(t2, whi + OF3, wlo + OF3, b_f3, y,  256, 128);

        zero_kernel<<<(NE + 255) / 256, 256>>>(s, NE);
        {
            long long tot = (long long)EE * 128;
            int blocks = (int)((tot + 255) / 256);
            scatter_kernel<<<blocks, 256>>>(edge_src + (size_t)d * EE,
                                            edge_dst + (size_t)d * EE,
                                            adj_vals + (size_t)d * EE,
                                            y, s, EE);
        }

        launch_gemm(s,  whi + OF1, wlo + OF1, b_f1, t1, 128, 256);
        launch_gemm(t1, whi + OF2, wlo + OF2, b_f2, t2, 256, 256);
        launch_gemm(t2, whi + OF3, wlo + OF3, b_f3, y,  256, 128);

        residual_kernel<<<(NE + 255) / 256, 256>>>(x, y, masks + (size_t)d * NN, NE);
    }
}

// round 4
// speedup vs baseline: 1.8766x; 1.1528x over previous
#include <cuda_runtime.h>
#include <cuda_bf16.h>
#include <cstdint>

#define NN 50000
#define EE 600000
#define DEPTH 8

// ---------------- scratch (alloc-free rule: __device__ globals) ----------------
// bf16 hi/lo activation buffers
__device__ __align__(16) __nv_bfloat16 g_nh[NN * 128], g_nl[NN * 128];   // split node_inputs
__device__ __align__(16) __nv_bfloat16 g_th1[NN * 256], g_tl1[NN * 256]; // t1
__device__ __align__(16) __nv_bfloat16 g_th2[NN * 256], g_tl2[NN * 256]; // t2
__device__ __align__(16) __nv_bfloat16 g_xh[NN * 128], g_xl[NN * 128];   // split x
__device__ __align__(16) __nv_bfloat16 g_sh[NN * 128], g_sl[NN * 128];   // split s
// fp32 buffers
__device__ __align__(16) float g_y[NN * 128];
__device__ __align__(16) float g_s[NN * 128];
// transposed + bf16-split weights: [M][K] layout, 6 matrices packed
__device__ __align__(16) __nv_bfloat16 g_wt_hi[262144];
__device__ __align__(16) __nv_bfloat16 g_wt_lo[262144];

// ---------------- helpers ----------------
__device__ __forceinline__ uint32_t smem_to_u32(const void* smem_ptr) {
    uint32_t addr;
    asm("{ .reg .u64 tmp; cvta.to.shared.u64 tmp, %1; cvt.u32.u64 %0, tmp; }"
        : "=r"(addr) : "l"(smem_ptr));
    return addr;
}

__device__ __forceinline__ void ldmx4(uint32_t* d, uint32_t addr) {
    asm volatile("ldmatrix.sync.aligned.m8n8.x4.shared.b16 {%0,%1,%2,%3}, [%4];"
                 : "=r"(d[0]), "=r"(d[1]), "=r"(d[2]), "=r"(d[3]) : "r"(addr));
}

__device__ __forceinline__ void mma16816(float* c, const uint32_t* a, const uint32_t* b) {
    asm volatile(
        "mma.sync.aligned.m16n8k16.row.col.f32.bf16.bf16.f32 "
        "{%0,%1,%2,%3},{%4,%5,%6,%7},{%8,%9},{%0,%1,%2,%3};"
        : "+f"(c[0]), "+f"(c[1]), "+f"(c[2]), "+f"(c[3])
        : "r"(a[0]), "r"(a[1]), "r"(a[2]), "r"(a[3]), "r"(b[0]), "r"(b[1]));
}

__device__ __forceinline__ void cp16(uint32_t smem_addr, const void* gptr, int srcbytes) {
    asm volatile("cp.async.cg.shared.global [%0], [%1], 16, %2;"
                 :: "r"(smem_addr), "l"(gptr), "r"(srcbytes) : "memory");
}

// swizzled byte offset within a 128x32 bf16 tile (row stride 64B, 16B groups XORed)
__device__ __forceinline__ uint32_t swz(int row, int c16) {
    return (uint32_t)(row * 64) + (uint32_t)(((c16 ^ ((row >> 1) & 3)) << 4));
}

__device__ __forceinline__ void split1(float v, __nv_bfloat16& h, __nv_bfloat16& l) {
    h = __float2bfloat16(v);
    l = __float2bfloat16(v - __bfloat162float(h));
}

// ---------------- mma.sync GEMM: C = lrelu(A @ W + b) ----------------
// A pre-split bf16 hi/lo [Nr,K]; W pre-transposed/split bf16 [M][K].
// 128x128 CTA tile, BK=32, cp.async 3-stage pipeline, 8 warps of 64x32.
// Outputs: Cf (fp32, optional) and/or Ch/Cl (bf16 hi/lo, optional).
__global__ __launch_bounds__(256, 1)
void gemm_mma(const __nv_bfloat16* __restrict__ Ahg, const __nv_bfloat16* __restrict__ Alg,
              const __nv_bfloat16* __restrict__ Bhg, const __nv_bfloat16* __restrict__ Blg,
              const float* __restrict__ bias,
              float* __restrict__ Cf, __nv_bfloat16* __restrict__ Ch,
              __nv_bfloat16* __restrict__ Cl, int Nrows, int K, int M)
{
    extern __shared__ char smem[];   // 3 stages x 32KB: [Ah 8K][Al 8K][Bh 8K][Bl 8K]
    const uint32_t sbase = smem_to_u32(smem);

    const int tid = threadIdx.x;
    const int wid = tid >> 5;
    const int lid = tid & 31;
    const int bm = blockIdx.y * 128;
    const int bn = blockIdx.x * 128;
    const int mo = (wid >> 2) * 64;       // warp m offset (0/64)
    const int no = (wid & 3) * 32;        // warp n offset (0/32/64/96)

    const int nchunks = K >> 5;

    // copy mapping: 8 x 16B groups per thread per stage
    // q = it*256 + tid in [0,2048): arr = q>>9 (Ah,Al,Bh,Bl), w=q&511, row=w>>2, c16=w&3
    const int arow = (tid & 511) >> 2;    // reused per it via +64 rows per it within arr

    float acc[4][4][4];
#pragma unroll
    for (int i = 0; i < 4; i++)
#pragma unroll
        for (int j = 0; j < 4; j++)
#pragma unroll
            for (int q = 0; q < 4; q++) acc[i][j][q] = 0.f;

    // tile issue lambda-equivalent
    auto issue = [&](int c) {
        const int k0 = c << 5;
        const uint32_t stg = (uint32_t)(c % 3) * 32768u;
#pragma unroll
        for (int it = 0; it < 8; ++it) {
            const int q = it * 256 + tid;
            const int arr = q >> 9;
            const int w = q & 511;
            const int row = w >> 2;
            const int c16 = w & 3;
            const uint32_t daddr = sbase + stg + (uint32_t)arr * 8192u + swz(row, c16);
            if (arr < 2) {
                const __nv_bfloat16* base = arr ? Alg : Ahg;
                const int grow = bm + row;
                const __nv_bfloat16* src = base + (size_t)(grow < Nrows ? grow : 0) * K + k0 + (c16 << 3);
                cp16(daddr, src, grow < Nrows ? 16 : 0);
            } else {
                const __nv_bfloat16* base = (arr == 3) ? Blg : Bhg;
                const __nv_bfloat16* src = base + (size_t)(bn + row) * K + k0 + (c16 << 3);
                cp16(daddr, src, 16);
            }
        }
        asm volatile("cp.async.commit_group;" ::: "memory");
    };

    // prologue: 2 stages in flight
    issue(0);
    if (nchunks > 1) issue(1);

    const int lrow = lid & 15;
    const int lc = lid >> 4;

    for (int c = 0; c < nchunks; ++c) {
        if (c + 2 < nchunks) {
            issue(c + 2);
            asm volatile("cp.async.wait_group 2;" ::: "memory");
        } else if (c + 1 < nchunks) {
            asm volatile("cp.async.wait_group 1;" ::: "memory");
        } else {
            asm volatile("cp.async.wait_group 0;" ::: "memory");
        }
        __syncthreads();

        const uint32_t Ah = sbase + (uint32_t)(c % 3) * 32768u;
        const uint32_t Al = Ah + 8192u;
        const uint32_t Bh_ = Ah + 16384u;
        const uint32_t Bl_ = Ah + 24576u;

#pragma unroll
        for (int ks = 0; ks < 2; ++ks) {
            const int cA = (ks << 1) + lc;
            uint32_t afh[4][4], afl[4][4];
#pragma unroll
            for (int i = 0; i < 4; ++i) {
                const int row = mo + i * 16 + lrow;
                const uint32_t so = swz(row, cA);
                ldmx4(afh[i], Ah + so);
                ldmx4(afl[i], Al + so);
            }
            uint32_t bfh[4][2], bfl[4][2];
#pragma unroll
            for (int jj = 0; jj < 2; ++jj) {
                const int row = no + jj * 16 + lrow;
                const uint32_t so = swz(row, cA);
                uint32_t r4[4];
                ldmx4(r4, Bh_ + so);
                bfh[jj * 2 + 0][0] = r4[0]; bfh[jj * 2 + 0][1] = r4[2];
                bfh[jj * 2 + 1][0] = r4[1]; bfh[jj * 2 + 1][1] = r4[3];
                ldmx4(r4, Bl_ + so);
                bfl[jj * 2 + 0][0] = r4[0]; bfl[jj * 2 + 0][1] = r4[2];
                bfl[jj * 2 + 1][0] = r4[1]; bfl[jj * 2 + 1][1] = r4[3];
            }
#pragma unroll
            for (int i = 0; i < 4; ++i)
#pragma unroll
                for (int j = 0; j < 4; ++j) {
                    mma16816(acc[i][j], afh[i], bfh[j]);
                    mma16816(acc[i][j], afh[i], bfl[j]);
                    mma16816(acc[i][j], afl[i], bfh[j]);
                }
        }
        __syncthreads();
    }

    // ---- epilogue: bias + leaky-relu; write fp32 and/or bf16 hi/lo ----
    const int g = lid >> 2;
    const int t2c = (lid & 3) << 1;
#pragma unroll
    for (int i = 0; i < 4; ++i) {
        const int row0 = bm + mo + i * 16 + g;
        const int row1 = row0 + 8;
#pragma unroll
        for (int j = 0; j < 4; ++j) {
            const int col = bn + no + j * 8 + t2c;
            const float2 bv = *(const float2*)(bias + col);
#pragma unroll
            for (int h = 0; h < 2; ++h) {
                const int row = h ? row1 : row0;
                if (row >= Nrows) continue;
                float2 o;
                o.x = acc[i][j][h * 2 + 0] + bv.x;
                o.y = acc[i][j][h * 2 + 1] + bv.y;
                o.x = o.x >= 0.f ? o.x : 0.01f * o.x;
                o.y = o.y >= 0.f ? o.y : 0.01f * o.y;
                const size_t off = (size_t)row * M + col;
                if (Cf) *(float2*)(Cf + off) = o;
                if (Ch) {
                    __nv_bfloat16 hx, lx, hy, ly;
                    split1(o.x, hx, lx);
                    split1(o.y, hy, ly);
                    *(__nv_bfloat162*)(Ch + off) = __nv_bfloat162(hx, hy);
                    *(__nv_bfloat162*)(Cl + off) = __nv_bfloat162(lx, ly);
                }
            }
        }
    }
}

// ---------------- weight prep: transpose + bf16 split ----------------
__global__ void prep_w(const float* __restrict__ W, __nv_bfloat16* __restrict__ hi,
                       __nv_bfloat16* __restrict__ lo, int K, int M)
{
    int idx = blockIdx.x * blockDim.x + threadIdx.x;
    if (idx >= K * M) return;
    int k = idx / M, m = idx - k * M;
    float v = W[idx];
    __nv_bfloat16 h = __float2bfloat16(v);
    hi[(size_t)m * K + k] = h;
    lo[(size_t)m * K + k] = __float2bfloat16(v - __bfloat162float(h));
}

// ---------------- split fp32 -> bf16 hi/lo (float4 wide) ----------------
__global__ void split_kernel(const float* __restrict__ in, __nv_bfloat16* __restrict__ hi,
                             __nv_bfloat16* __restrict__ lo, int n4)
{
    int i = blockIdx.x * blockDim.x + threadIdx.x;
    if (i >= n4) return;
    float4 v = ((const float4*)in)[i];
    __nv_bfloat16 h0, l0, h1, l1, h2, l2, h3, l3;
    split1(v.x, h0, l0); split1(v.y, h1, l1);
    split1(v.z, h2, l2); split1(v.w, h3, l3);
    ((__nv_bfloat162*)hi)[i * 2 + 0] = __nv_bfloat162(h0, h1);
    ((__nv_bfloat162*)hi)[i * 2 + 1] = __nv_bfloat162(h2, h3);
    ((__nv_bfloat162*)lo)[i * 2 + 0] = __nv_bfloat162(l0, l1);
    ((__nv_bfloat162*)lo)[i * 2 + 1] = __nv_bfloat162(l2, l3);
}

// ---------------- zero / scatter / residual ----------------
__global__ void zero_kernel(float4* __restrict__ p, int n4)
{
    int i = blockIdx.x * blockDim.x + threadIdx.x;
    if (i < n4) p[i] = make_float4(0.f, 0.f, 0.f, 0.f);
}

// one thread per (edge, 4 dims): 32 threads/edge
__global__ void scatter_kernel(const int* __restrict__ src, const int* __restrict__ dst,
                               const float* __restrict__ vals,
                               const float* __restrict__ y, float* __restrict__ out,
                               int E)
{
    int gid = blockIdx.x * blockDim.x + threadIdx.x;
    int e = gid >> 5;
    int d4 = (gid & 31) << 2;
    if (e >= E) return;
    float v = vals[e];
    int s = src[e];
    int t = dst[e];
    float4 yv = *(const float4*)(y + (size_t)t * 128 + d4);
    float* o = out + (size_t)s * 128 + d4;
    atomicAdd(o + 0, v * yv.x);
    atomicAdd(o + 1, v * yv.y);
    atomicAdd(o + 2, v * yv.z);
    atomicAdd(o + 3, v * yv.w);
}

// x += mask*y (float4) and write split(x) to xh/xl
__global__ void residual_kernel(float* __restrict__ x, const float* __restrict__ y,
                                const float* __restrict__ mask,
                                __nv_bfloat16* __restrict__ xh, __nv_bfloat16* __restrict__ xl,
                                int n4)
{
    int i = blockIdx.x * blockDim.x + threadIdx.x;
    if (i >= n4) return;
    float m = mask[i >> 5];
    float4 xv = ((const float4*)x)[i];
    float4 yv = ((const float4*)y)[i];
    xv.x += m * yv.x; xv.y += m * yv.y; xv.z += m * yv.z; xv.w += m * yv.w;
    ((float4*)x)[i] = xv;
    __nv_bfloat16 h0, l0, h1, l1, h2, l2, h3, l3;
    split1(xv.x, h0, l0); split1(xv.y, h1, l1);
    split1(xv.z, h2, l2); split1(xv.w, h3, l3);
    ((__nv_bfloat162*)xh)[i * 2 + 0] = __nv_bfloat162(h0, h1);
    ((__nv_bfloat162*)xh)[i * 2 + 1] = __nv_bfloat162(h2, h3);
    ((__nv_bfloat162*)xl)[i * 2 + 0] = __nv_bfloat162(l0, l1);
    ((__nv_bfloat162*)xl)[i * 2 + 1] = __nv_bfloat162(l2, l3);
}

// ---------------- host orchestration ----------------
static const int GEMM_SMEM = 98304;   // 3 stages x 32KB

static inline void launch_gemm(const __nv_bfloat16* Ah, const __nv_bfloat16* Al,
                               const __nv_bfloat16* Bh, const __nv_bfloat16* Bl,
                               const float* bias, float* Cf, __nv_bfloat16* Ch,
                               __nv_bfloat16* Cl, int K, int M)
{
    dim3 grid(M / 128, (NN + 127) / 128);
    gemm_mma<<<grid, 256, GEMM_SMEM>>>(Ah, Al, Bh, Bl, bias, Cf, Ch, Cl, NN, K, M);
}

extern "C" void kernel_launch(void* const* d_in, const int* in_sizes, int n_in,
                              void* d_out, int out_size)
{
    const float* node_inputs = (const float*)d_in[0];
    const int*   edge_src    = (const int*)  d_in[1];
    const int*   edge_dst    = (const int*)  d_in[2];
    const float* adj_vals    = (const float*)d_in[3];
    const float* masks       = (const float*)d_in[4];
    const float* W_h1 = (const float*)d_in[5];
    const float* b_h1 = (const float*)d_in[6];
    const float* W_h2 = (const float*)d_in[7];
    const float* b_h2 = (const float*)d_in[8];
    const float* W_h3 = (const float*)d_in[9];
    const float* b_h3 = (const float*)d_in[10];
    const float* W_f1 = (const float*)d_in[11];
    const float* b_f1 = (const float*)d_in[12];
    const float* W_f2 = (const float*)d_in[13];
    const float* b_f2 = (const float*)d_in[14];
    const float* W_f3 = (const float*)d_in[15];
    const float* b_f3 = (const float*)d_in[16];

    float* x = (float*)d_out;

    float *y, *s;
    __nv_bfloat16 *whi, *wlo, *nh, *nl, *th1, *tl1, *th2, *tl2, *xh, *xl, *sh, *sl;
    cudaGetSymbolAddress((void**)&y,   g_y);
    cudaGetSymbolAddress((void**)&s,   g_s);
    cudaGetSymbolAddress((void**)&whi, g_wt_hi);
    cudaGetSymbolAddress((void**)&wlo, g_wt_lo);
    cudaGetSymbolAddress((void**)&nh,  g_nh);
    cudaGetSymbolAddress((void**)&nl,  g_nl);
    cudaGetSymbolAddress((void**)&th1, g_th1);
    cudaGetSymbolAddress((void**)&tl1, g_tl1);
    cudaGetSymbolAddress((void**)&th2, g_th2);
    cudaGetSymbolAddress((void**)&tl2, g_tl2);
    cudaGetSymbolAddress((void**)&xh,  g_xh);
    cudaGetSymbolAddress((void**)&xl,  g_xl);
    cudaGetSymbolAddress((void**)&sh,  g_sh);
    cudaGetSymbolAddress((void**)&sl,  g_sl);

    cudaFuncSetAttribute(gemm_mma, cudaFuncAttributeMaxDynamicSharedMemorySize, GEMM_SMEM);

    // packed offsets for the 6 transposed/split weight matrices
    const int OH1 = 0, OH2 = 32768, OH3 = 98304, OF1 = 131072, OF2 = 163840, OF3 = 229376;

    prep_w<<<(128 * 256 + 255) / 256, 256>>>(W_h1, whi + OH1, wlo + OH1, 128, 256);
    prep_w<<<(256 * 256 + 255) / 256, 256>>>(W_h2, whi + OH2, wlo + OH2, 256, 256);
    prep_w<<<(256 * 128 + 255) / 256, 256>>>(W_h3, whi + OH3, wlo + OH3, 256, 128);
    prep_w<<<(128 * 256 + 255) / 256, 256>>>(W_f1, whi + OF1, wlo + OF1, 128, 256);
    prep_w<<<(256 * 256 + 255) / 256, 256>>>(W_f2, whi + OF2, wlo + OF2, 256, 256);
    prep_w<<<(256 * 128 + 255) / 256, 256>>>(W_f3, whi + OF3, wlo + OF3, 256, 128);

    const int NE = NN * 128;           // 6.4M
    const int NE4 = NE / 4;

    // split node inputs
    split_kernel<<<(NE4 + 255) / 256, 256>>>(node_inputs, nh, nl, NE4);

    // embedding MLP: x = mlp3(node_inputs; W_h*)  (x fp32 + xh/xl)
    launch_gemm(nh,  nl,  whi + OH1, wlo + OH1, b_h1, nullptr, th1, tl1, 128, 256);
    launch_gemm(th1, tl1, whi + OH2, wlo + OH2, b_h2, nullptr, th2, tl2, 256, 256);
    launch_gemm(th2, tl2, whi + OH3, wlo + OH3, b_h3, x, xh, xl, 256, 128);

    for (int d = 0; d < DEPTH; d++) {
        // y = mlp3(x)
        launch_gemm(xh,  xl,  whi + OF1, wlo + OF1, b_f1, nullptr, th1, tl1, 128, 256);
        launch_gemm(th1, tl1, whi + OF2, wlo + OF2, b_f2, nullptr, th2, tl2, 256, 256);
        launch_gemm(th2, tl2, whi + OF3, wlo + OF3, b_f3, y, nullptr, nullptr, 256, 128);

        // s = segment_sum(adj_vals * y[dst], src)
        zero_kernel<<<(NE4 + 255) / 256, 256>>>((float4*)s, NE4);
        {
            long long tot = (long long)EE * 32;
            int blocks = (int)((tot + 255) / 256);
            scatter_kernel<<<blocks, 256>>>(edge_src + (size_t)d * EE,
                                            edge_dst + (size_t)d * EE,
                                            adj_vals + (size_t)d * EE,
                                            y, s, EE);
        }
        split_kernel<<<(NE4 + 255) / 256, 256>>>(s, sh, sl, NE4);

        // y = mlp3(s)
        launch_gemm(sh,  sl,  whi + OF1, wlo + OF1, b_f1, nullptr, th1, tl1, 128, 256);
        launch_gemm(th1, tl1, whi + OF2, wlo + OF2, b_f2, nullptr, th2, tl2, 256, 256);
        launch_gemm(th2, tl2, whi + OF3, wlo + OF3, b_f3, y, nullptr, nullptr, 256, 128);

        // x += mask[d] * y ; refresh xh/xl
        residual_kernel<<<(NE4 + 255) / 256, 256>>>(x, y, masks + (size_t)d * NN,
                                                    xh, xl, NE4);
    }
}

// round 5
// speedup vs baseline: 2.1493x; 1.1453x over previous
#include <cuda_runtime.h>
#include <cuda_bf16.h>
#include <cstdint>

#define NN 50000
#define EE 600000
#define DEPTH 8

// ---------------- scratch (alloc-free rule: __device__ globals) ----------------
__device__ __align__(16) __nv_bfloat16 g_nh[NN * 128], g_nl[NN * 128];   // split node_inputs
__device__ __align__(16) __nv_bfloat16 g_xh[NN * 128], g_xl[NN * 128];   // split x
__device__ __align__(16) __nv_bfloat16 g_sh[NN * 128], g_sl[NN * 128];   // split s
__device__ __align__(16) float g_y[NN * 128];
__device__ __align__(16) float g_s[NN * 128];
// transposed + bf16-split weights: [M][K] layout, 6 matrices packed
__device__ __align__(16) __nv_bfloat16 g_wt_hi[262144];
__device__ __align__(16) __nv_bfloat16 g_wt_lo[262144];

// ---------------- helpers ----------------
__device__ __forceinline__ uint32_t smem_to_u32(const void* smem_ptr) {
    uint32_t addr;
    asm("{ .reg .u64 tmp; cvta.to.shared.u64 tmp, %1; cvt.u32.u64 %0, tmp; }"
        : "=r"(addr) : "l"(smem_ptr));
    return addr;
}

__device__ __forceinline__ void ldmx4(uint32_t* d, uint32_t addr) {
    asm volatile("ldmatrix.sync.aligned.m8n8.x4.shared.b16 {%0,%1,%2,%3}, [%4];"
                 : "=r"(d[0]), "=r"(d[1]), "=r"(d[2]), "=r"(d[3]) : "r"(addr));
}

__device__ __forceinline__ void mma16816(float* c, const uint32_t* a, const uint32_t* b) {
    asm volatile(
        "mma.sync.aligned.m16n8k16.row.col.f32.bf16.bf16.f32 "
        "{%0,%1,%2,%3},{%4,%5,%6,%7},{%8,%9},{%0,%1,%2,%3};"
        : "+f"(c[0]), "+f"(c[1]), "+f"(c[2]), "+f"(c[3])
        : "r"(a[0]), "r"(a[1]), "r"(a[2]), "r"(a[3]), "r"(b[0]), "r"(b[1]));
}

__device__ __forceinline__ void cp16(uint32_t smem_addr, const void* gptr, int srcbytes) {
    asm volatile("cp.async.cg.shared.global [%0], [%1], 16, %2;"
                 :: "r"(smem_addr), "l"(gptr), "r"(srcbytes) : "memory");
}
#define CP_COMMIT() asm volatile("cp.async.commit_group;" ::: "memory")
#define CP_WAIT(n)  asm volatile("cp.async.wait_group %0;" :: "n"(n) : "memory")

// swizzled byte offset within a 128x32 bf16 tile (row stride 64B, 16B groups XORed)
__device__ __forceinline__ uint32_t swz(int row, int c16) {
    return (uint32_t)(row * 64) + (uint32_t)(((c16 ^ ((row >> 1) & 3)) << 4));
}

__device__ __forceinline__ void split1(float v, __nv_bfloat16& h, __nv_bfloat16& l) {
    h = __float2bfloat16(v);
    l = __float2bfloat16(v - __bfloat162float(h));
}

// ---- one K=32 chunk of split-bf16 MMA. A tile at Abase {hi,+8192 lo};
// ---- NB n-blocks at Bbase + nb*16384 {hi,+8192 lo}.
template<int NB>
__device__ __forceinline__ void chunk_mma(uint32_t Abase, uint32_t Bbase,
                                          int mo, int no, int lid,
                                          float acc[NB][4][4][4])
{
    const int lrow = lid & 15;
    const int lc = lid >> 4;
#pragma unroll
    for (int ks = 0; ks < 2; ++ks) {
        const int cA = (ks << 1) + lc;
        uint32_t afh[4][4], afl[4][4];
#pragma unroll
        for (int i = 0; i < 4; ++i) {
            const int row = mo + i * 16 + lrow;
            const uint32_t so = swz(row, cA);
            ldmx4(afh[i], Abase + so);
            ldmx4(afl[i], Abase + 8192u + so);
        }
#pragma unroll
        for (int nb = 0; nb < NB; ++nb) {
            uint32_t bfh[4][2], bfl[4][2];
#pragma unroll
            for (int jj = 0; jj < 2; ++jj) {
                const int row = no + jj * 16 + lrow;
                const uint32_t so = swz(row, cA) + (uint32_t)nb * 16384u;
                uint32_t r4[4];
                ldmx4(r4, Bbase + so);
                bfh[jj * 2 + 0][0] = r4[0]; bfh[jj * 2 + 0][1] = r4[2];
                bfh[jj * 2 + 1][0] = r4[1]; bfh[jj * 2 + 1][1] = r4[3];
                ldmx4(r4, Bbase + 8192u + so);
                bfl[jj * 2 + 0][0] = r4[0]; bfl[jj * 2 + 0][1] = r4[2];
                bfl[jj * 2 + 1][0] = r4[1]; bfl[jj * 2 + 1][1] = r4[3];
            }
#pragma unroll
            for (int i = 0; i < 4; ++i)
#pragma unroll
                for (int j = 0; j < 4; ++j) {
                    mma16816(acc[nb][i][j], afh[i], bfh[j]);
                    mma16816(acc[nb][i][j], afh[i], bfl[j]);
                    mma16816(acc[nb][i][j], afl[i], bfh[j]);
                }
        }
    }
}

// ---- epilogue into act smem: bias + leaky-relu + bf16 split, swizzled layout ----
template<int NB>
__device__ __forceinline__ void epi_to_act(float acc[NB][4][4][4], const float* bias,
                                           uint32_t act, int mo, int no, int lid)
{
    const int g = lid >> 2;
    const int t2c = (lid & 3) << 1;
#pragma unroll
    for (int nb = 0; nb < NB; ++nb)
#pragma unroll
    for (int i = 0; i < 4; ++i) {
        const int row0 = mo + i * 16 + g;
#pragma unroll
        for (int j = 0; j < 4; ++j) {
            const int col = nb * 128 + no + j * 8 + t2c;
            const float2 bv = *(const float2*)(bias + col);
            const uint32_t cbase = act + (uint32_t)(col >> 5) * 16384u;
            const int c16 = (col & 31) >> 3;
            const uint32_t sub = (uint32_t)((col & 7) << 1);
#pragma unroll
            for (int h = 0; h < 2; ++h) {
                const int row = row0 + h * 8;
                float ox = acc[nb][i][j][h * 2 + 0] + bv.x;
                float oy = acc[nb][i][j][h * 2 + 1] + bv.y;
                ox = ox >= 0.f ? ox : 0.01f * ox;
                oy = oy >= 0.f ? oy : 0.01f * oy;
                __nv_bfloat16 hx, lx, hy, ly;
                split1(ox, hx, lx);
                split1(oy, hy, ly);
                uint32_t hp = (uint32_t)__bfloat16_as_ushort(hx) | ((uint32_t)__bfloat16_as_ushort(hy) << 16);
                uint32_t lp = (uint32_t)__bfloat16_as_ushort(lx) | ((uint32_t)__bfloat16_as_ushort(ly) << 16);
                const uint32_t ad = cbase + swz(row, c16) + sub;
                asm volatile("st.shared.b32 [%0], %1;" :: "r"(ad), "r"(hp) : "memory");
                asm volatile("st.shared.b32 [%0], %1;" :: "r"(ad + 8192u), "r"(lp) : "memory");
            }
        }
    }
}

// ---------------- fused MLP3: out = lrelu(lrelu(lrelu(A@W1+b1)@W2+b2)@W3+b3) ----
// A pre-split bf16 hi/lo [Nr,128]; W1[256][128], W2[256][256], W3[128][256] (all [M][K] hi/lo).
// act smem holds the 128x256 intermediate (8 K-chunks x [hi 8K|lo 8K]).
__global__ __launch_bounds__(256, 1)
void fused_mlp3(const __nv_bfloat16* __restrict__ Ahg, const __nv_bfloat16* __restrict__ Alg,
                const __nv_bfloat16* __restrict__ W1h, const __nv_bfloat16* __restrict__ W1l,
                const __nv_bfloat16* __restrict__ W2h, const __nv_bfloat16* __restrict__ W2l,
                const __nv_bfloat16* __restrict__ W3h, const __nv_bfloat16* __restrict__ W3l,
                const float* __restrict__ b1, const float* __restrict__ b2,
                const float* __restrict__ b3,
                float* __restrict__ Cf, __nv_bfloat16* __restrict__ Ch,
                __nv_bfloat16* __restrict__ Cl, int Nrows)
{
    extern __shared__ char smem[];
    const uint32_t sb = smem_to_u32(smem);
    const uint32_t ACT = sb;                 // 128KB: chunk c at +c*16384 {hi, +8192 lo}
    const uint32_t STG = sb + 131072u;       // 96KB stage region

    const int tid = threadIdx.x;
    const int wid = tid >> 5;
    const int lid = tid & 31;
    const int bm = blockIdx.x * 128;
    const int mo = (wid >> 2) * 64;
    const int no = (wid & 3) * 32;

    float acc[2][4][4][4];

    // ================= layer 1: K=128 (4 chunks), 2 stages x 48KB =================
    auto issue1 = [&](int c) {
        const int k0 = c << 5;
        const uint32_t st = STG + (uint32_t)(c & 1) * 49152u;
#pragma unroll
        for (int it = 0; it < 12; ++it) {
            const int q = it * 256 + tid;
            const int reg = q >> 9;            // 0:Ah 1:Al 2:B0h 3:B0l 4:B1h 5:B1l
            const int w = q & 511;
            const int row = w >> 2;
            const int c16 = w & 3;
            const uint32_t daddr = st + (uint32_t)reg * 8192u + swz(row, c16);
            if (reg < 2) {
                const __nv_bfloat16* base = reg ? Alg : Ahg;
                const int grow = bm + row;
                const __nv_bfloat16* src = base + (size_t)(grow < Nrows ? grow : 0) * 128 + k0 + (c16 << 3);
                cp16(daddr, src, grow < Nrows ? 16 : 0);
            } else {
                const int nb = (reg - 2) >> 1;
                const __nv_bfloat16* base = ((reg - 2) & 1) ? W1l : W1h;
                const __nv_bfloat16* src = base + (size_t)(nb * 128 + row) * 128 + k0 + (c16 << 3);
                cp16(daddr, src, 16);
            }
        }
        CP_COMMIT();
    };

#pragma unroll
    for (int nb = 0; nb < 2; ++nb)
#pragma unroll
        for (int i = 0; i < 4; ++i)
#pragma unroll
            for (int j = 0; j < 4; ++j)
#pragma unroll
                for (int q = 0; q < 4; ++q) acc[nb][i][j][q] = 0.f;

    issue1(0);
    issue1(1);
    for (int c = 0; c < 4; ++c) {
        if (c < 3) { CP_WAIT(1); } else { CP_WAIT(0); }
        __syncthreads();
        const uint32_t st = STG + (uint32_t)(c & 1) * 49152u;
        chunk_mma<2>(st, st + 16384u, mo, no, lid, acc);
        __syncthreads();
        if (c + 2 < 4) issue1(c + 2);
    }
    epi_to_act<2>(acc, b1, ACT, mo, no, lid);
    __syncthreads();

    // ================= layer 2: K=256 (8 chunks), 3 stages x 32KB =================
    auto issue2 = [&](int c) {
        const int k0 = c << 5;
        const uint32_t st = STG + (uint32_t)(c % 3) * 32768u;
#pragma unroll
        for (int it = 0; it < 8; ++it) {
            const int q = it * 256 + tid;
            const int reg = q >> 9;            // 0:B0h 1:B0l 2:B1h 3:B1l
            const int w = q & 511;
            const int row = w >> 2;
            const int c16 = w & 3;
            const uint32_t daddr = st + (uint32_t)reg * 8192u + swz(row, c16);
            const int nb = reg >> 1;
            const __nv_bfloat16* base = (reg & 1) ? W2l : W2h;
            const __nv_bfloat16* src = base + (size_t)(nb * 128 + row) * 256 + k0 + (c16 << 3);
            cp16(daddr, src, 16);
        }
        CP_COMMIT();
    };

#pragma unroll
    for (int nb = 0; nb < 2; ++nb)
#pragma unroll
        for (int i = 0; i < 4; ++i)
#pragma unroll
            for (int j = 0; j < 4; ++j)
#pragma unroll
                for (int q = 0; q < 4; ++q) acc[nb][i][j][q] = 0.f;

    issue2(0);
    issue2(1);
    for (int c = 0; c < 8; ++c) {
        if (c + 2 < 8) { issue2(c + 2); CP_WAIT(2); }
        else if (c + 1 < 8) { CP_WAIT(1); }
        else { CP_WAIT(0); }
        __syncthreads();
        chunk_mma<2>(ACT + (uint32_t)c * 16384u, STG + (uint32_t)(c % 3) * 32768u,
                     mo, no, lid, acc);
        __syncthreads();
    }
    epi_to_act<2>(acc, b2, ACT, mo, no, lid);
    __syncthreads();

    // ================= layer 3: K=256 (8 chunks), M=128, 3 stages x 16KB ==========
    auto issue3 = [&](int c) {
        const int k0 = c << 5;
        const uint32_t st = STG + (uint32_t)(c % 3) * 16384u;
#pragma unroll
        for (int it = 0; it < 4; ++it) {
            const int q = it * 256 + tid;
            const int reg = q >> 9;            // 0:Bh 1:Bl
            const int w = q & 511;
            const int row = w >> 2;
            const int c16 = w & 3;
            const uint32_t daddr = st + (uint32_t)reg * 8192u + swz(row, c16);
            const __nv_bfloat16* base = reg ? W3l : W3h;
            const __nv_bfloat16* src = base + (size_t)row * 256 + k0 + (c16 << 3);
            cp16(daddr, src, 16);
        }
        CP_COMMIT();
    };

    float (&acc1)[1][4][4][4] = *reinterpret_cast<float(*)[1][4][4][4]>(acc);
#pragma unroll
    for (int i = 0; i < 4; ++i)
#pragma unroll
        for (int j = 0; j < 4; ++j)
#pragma unroll
            for (int q = 0; q < 4; ++q) acc1[0][i][j][q] = 0.f;

    issue3(0);
    issue3(1);
    for (int c = 0; c < 8; ++c) {
        if (c + 2 < 8) { issue3(c + 2); CP_WAIT(2); }
        else if (c + 1 < 8) { CP_WAIT(1); }
        else { CP_WAIT(0); }
        __syncthreads();
        chunk_mma<1>(ACT + (uint32_t)c * 16384u, STG + (uint32_t)(c % 3) * 16384u,
                     mo, no, lid, acc1);
        __syncthreads();
    }

    // ---- final epilogue: bias + leaky-relu, global stores ----
    {
        const int g = lid >> 2;
        const int t2c = (lid & 3) << 1;
#pragma unroll
        for (int i = 0; i < 4; ++i) {
            const int row0 = bm + mo + i * 16 + g;
#pragma unroll
            for (int j = 0; j < 4; ++j) {
                const int col = no + j * 8 + t2c;
                const float2 bv = *(const float2*)(b3 + col);
#pragma unroll
                for (int h = 0; h < 2; ++h) {
                    const int row = row0 + h * 8;
                    if (row >= Nrows) continue;
                    float2 o;
                    o.x = acc1[0][i][j][h * 2 + 0] + bv.x;
                    o.y = acc1[0][i][j][h * 2 + 1] + bv.y;
                    o.x = o.x >= 0.f ? o.x : 0.01f * o.x;
                    o.y = o.y >= 0.f ? o.y : 0.01f * o.y;
                    const size_t off = (size_t)row * 128 + col;
                    if (Cf) *(float2*)(Cf + off) = o;
                    if (Ch) {
                        __nv_bfloat16 hx, lx, hy, ly;
                        split1(o.x, hx, lx);
                        split1(o.y, hy, ly);
                        *(__nv_bfloat162*)(Ch + off) = __nv_bfloat162(hx, hy);
                        *(__nv_bfloat162*)(Cl + off) = __nv_bfloat162(lx, ly);
                    }
                }
            }
        }
    }
}

// ---------------- weight prep: transpose + bf16 split ----------------
__global__ void prep_w(const float* __restrict__ W, __nv_bfloat16* __restrict__ hi,
                       __nv_bfloat16* __restrict__ lo, int K, int M)
{
    int idx = blockIdx.x * blockDim.x + threadIdx.x;
    if (idx >= K * M) return;
    int k = idx / M, m = idx - k * M;
    float v = W[idx];
    __nv_bfloat16 h = __float2bfloat16(v);
    hi[(size_t)m * K + k] = h;
    lo[(size_t)m * K + k] = __float2bfloat16(v - __bfloat162float(h));
}

// ---------------- split fp32 -> bf16 hi/lo (float4 wide) ----------------
__global__ void split_kernel(const float* __restrict__ in, __nv_bfloat16* __restrict__ hi,
                             __nv_bfloat16* __restrict__ lo, int n4)
{
    int i = blockIdx.x * blockDim.x + threadIdx.x;
    if (i >= n4) return;
    float4 v = ((const float4*)in)[i];
    __nv_bfloat16 h0, l0, h1, l1, h2, l2, h3, l3;
    split1(v.x, h0, l0); split1(v.y, h1, l1);
    split1(v.z, h2, l2); split1(v.w, h3, l3);
    ((__nv_bfloat162*)hi)[i * 2 + 0] = __nv_bfloat162(h0, h1);
    ((__nv_bfloat162*)hi)[i * 2 + 1] = __nv_bfloat162(h2, h3);
    ((__nv_bfloat162*)lo)[i * 2 + 0] = __nv_bfloat162(l0, l1);
    ((__nv_bfloat162*)lo)[i * 2 + 1] = __nv_bfloat162(l2, l3);
}

// ---------------- zero / scatter / residual ----------------
__global__ void zero_kernel(float4* __restrict__ p, int n4)
{
    int i = blockIdx.x * blockDim.x + threadIdx.x;
    if (i < n4) p[i] = make_float4(0.f, 0.f, 0.f, 0.f);
}

// one thread per (edge, 4 dims): 32 threads/edge
__global__ void scatter_kernel(const int* __restrict__ src, const int* __restrict__ dst,
                               const float* __restrict__ vals,
                               const float* __restrict__ y, float* __restrict__ out,
                               int E)
{
    int gid = blockIdx.x * blockDim.x + threadIdx.x;
    int e = gid >> 5;
    int d4 = (gid & 31) << 2;
    if (e >= E) return;
    float v = vals[e];
    int s = src[e];
    int t = dst[e];
    float4 yv = *(const float4*)(y + (size_t)t * 128 + d4);
    float* o = out + (size_t)s * 128 + d4;
    atomicAdd(o + 0, v * yv.x);
    atomicAdd(o + 1, v * yv.y);
    atomicAdd(o + 2, v * yv.z);
    atomicAdd(o + 3, v * yv.w);
}

// x += mask*y (float4) and write split(x) to xh/xl
__global__ void residual_kernel(float* __restrict__ x, const float* __restrict__ y,
                                const float* __restrict__ mask,
                                __nv_bfloat16* __restrict__ xh, __nv_bfloat16* __restrict__ xl,
                                int n4)
{
    int i = blockIdx.x * blockDim.x + threadIdx.x;
    if (i >= n4) return;
    float m = mask[i >> 5];
    float4 xv = ((const float4*)x)[i];
    float4 yv = ((const float4*)y)[i];
    xv.x += m * yv.x; xv.y += m * yv.y; xv.z += m * yv.z; xv.w += m * yv.w;
    ((float4*)x)[i] = xv;
    __nv_bfloat16 h0, l0, h1, l1, h2, l2, h3, l3;
    split1(xv.x, h0, l0); split1(xv.y, h1, l1);
    split1(xv.z, h2, l2); split1(xv.w, h3, l3);
    ((__nv_bfloat162*)xh)[i * 2 + 0] = __nv_bfloat162(h0, h1);
    ((__nv_bfloat162*)xh)[i * 2 + 1] = __nv_bfloat162(h2, h3);
    ((__nv_bfloat162*)xl)[i * 2 + 0] = __nv_bfloat162(l0, l1);
    ((__nv_bfloat162*)xl)[i * 2 + 1] = __nv_bfloat162(l2, l3);
}

// ---------------- host orchestration ----------------
static const int FUSED_SMEM = 131072 + 98304;   // act 128KB + stages 96KB = 224KB

extern "C" void kernel_launch(void* const* d_in, const int* in_sizes, int n_in,
                              void* d_out, int out_size)
{
    const float* node_inputs = (const float*)d_in[0];
    const int*   edge_src    = (const int*)  d_in[1];
    const int*   edge_dst    = (const int*)  d_in[2];
    const float* adj_vals    = (const float*)d_in[3];
    const float* masks       = (const float*)d_in[4];
    const float* W_h1 = (const float*)d_in[5];
    const float* b_h1 = (const float*)d_in[6];
    const float* W_h2 = (const float*)d_in[7];
    const float* b_h2 = (const float*)d_in[8];
    const float* W_h3 = (const float*)d_in[9];
    const float* b_h3 = (const float*)d_in[10];
    const float* W_f1 = (const float*)d_in[11];
    const float* b_f1 = (const float*)d_in[12];
    const float* W_f2 = (const float*)d_in[13];
    const float* b_f2 = (const float*)d_in[14];
    const float* W_f3 = (const float*)d_in[15];
    const float* b_f3 = (const float*)d_in[16];

    float* x = (float*)d_out;

    float *y, *s;
    __nv_bfloat16 *whi, *wlo, *nh, *nl, *xh, *xl, *sh, *sl;
    cudaGetSymbolAddress((void**)&y,   g_y);
    cudaGetSymbolAddress((void**)&s,   g_s);
    cudaGetSymbolAddress((void**)&whi, g_wt_hi);
    cudaGetSymbolAddress((void**)&wlo, g_wt_lo);
    cudaGetSymbolAddress((void**)&nh,  g_nh);
    cudaGetSymbolAddress((void**)&nl,  g_nl);
    cudaGetSymbolAddress((void**)&xh,  g_xh);
    cudaGetSymbolAddress((void**)&xl,  g_xl);
    cudaGetSymbolAddress((void**)&sh,  g_sh);
    cudaGetSymbolAddress((void**)&sl,  g_sl);

    cudaFuncSetAttribute(fused_mlp3, cudaFuncAttributeMaxDynamicSharedMemorySize, FUSED_SMEM);

    // packed offsets for the 6 transposed/split weight matrices
    const int OH1 = 0, OH2 = 32768, OH3 = 98304, OF1 = 131072, OF2 = 163840, OF3 = 229376;

    prep_w<<<(128 * 256 + 255) / 256, 256>>>(W_h1, whi + OH1, wlo + OH1, 128, 256);
    prep_w<<<(256 * 256 + 255) / 256, 256>>>(W_h2, whi + OH2, wlo + OH2, 256, 256);
    prep_w<<<(256 * 128 + 255) / 256, 256>>>(W_h3, whi + OH3, wlo + OH3, 256, 128);
    prep_w<<<(128 * 256 + 255) / 256, 256>>>(W_f1, whi + OF1, wlo + OF1, 128, 256);
    prep_w<<<(256 * 256 + 255) / 256, 256>>>(W_f2, whi + OF2, wlo + OF2, 256, 256);
    prep_w<<<(256 * 128 + 255) / 256, 256>>>(W_f3, whi + OF3, wlo + OF3, 256, 128);

    const int NE = NN * 128;
    const int NE4 = NE / 4;
    const int GRID = (NN + 127) / 128;   // 391

    // split node inputs
    split_kernel<<<(NE4 + 255) / 256, 256>>>(node_inputs, nh, nl, NE4);

    // embedding MLP: x = mlp3(node_inputs; W_h*)  -> x fp32 + xh/xl
    fused_mlp3<<<GRID, 256, FUSED_SMEM>>>(nh, nl,
        whi + OH1, wlo + OH1, whi + OH2, wlo + OH2, whi + OH3, wlo + OH3,
        b_h1, b_h2, b_h3, x, xh, xl, NN);

    for (int d = 0; d < DEPTH; d++) {
        // y = mlp3(x)
        fused_mlp3<<<GRID, 256, FUSED_SMEM>>>(xh, xl,
            whi + OF1, wlo + OF1, whi + OF2, wlo + OF2, whi + OF3, wlo + OF3,
            b_f1, b_f2, b_f3, y, nullptr, nullptr, NN);

        // s = segment_sum(adj_vals * y[dst], src)
        zero_kernel<<<(NE4 + 255) / 256, 256>>>((float4*)s, NE4);
        {
            long long tot = (long long)EE * 32;
            int blocks = (int)((tot + 255) / 256);
            scatter_kernel<<<blocks, 256>>>(edge_src + (size_t)d * EE,
                                            edge_dst + (size_t)d * EE,
                                            adj_vals + (size_t)d * EE,
                                            y, s, EE);
        }
        split_kernel<<<(NE4 + 255) / 256, 256>>>(s, sh, sl, NE4);

        // y = mlp3(s)
        fused_mlp3<<<GRID, 256, FUSED_SMEM>>>(sh, sl,
            whi + OF1, wlo + OF1, whi + OF2, wlo + OF2, whi + OF3, wlo + OF3,
            b_f1, b_f2, b_f3, y, nullptr, nullptr, NN);

        // x += mask[d] * y ; refresh xh/xl
        residual_kernel<<<(NE4 + 255) / 256, 256>>>(x, y, masks + (size_t)d * NN,
                                                    xh, xl, NE4);
    }
}

// round 6
// speedup vs baseline: 2.5983x; 1.2089x over previous
#include <cuda_runtime.h>
#include <cuda_bf16.h>
#include <cstdint>

#define NN 50000
#define EE 600000
#define DEPTH 8

// ---------------- scratch (alloc-free rule: __device__ globals) ----------------
__device__ __align__(16) float g_y[NN * 128];
__device__ __align__(16) float g_s[NN * 128];
// transposed + bf16-split weights: [M][K] layout, 6 matrices packed
__device__ __align__(16) __nv_bfloat16 g_wt_hi[262144];
__device__ __align__(16) __nv_bfloat16 g_wt_lo[262144];

// ---------------- helpers ----------------
__device__ __forceinline__ uint32_t smem_to_u32(const void* smem_ptr) {
    uint32_t addr;
    asm("{ .reg .u64 tmp; cvta.to.shared.u64 tmp, %1; cvt.u32.u64 %0, tmp; }"
        : "=r"(addr) : "l"(smem_ptr));
    return addr;
}

__device__ __forceinline__ void ldmx4(uint32_t* d, uint32_t addr) {
    asm volatile("ldmatrix.sync.aligned.m8n8.x4.shared.b16 {%0,%1,%2,%3}, [%4];"
                 : "=r"(d[0]), "=r"(d[1]), "=r"(d[2]), "=r"(d[3]) : "r"(addr));
}

__device__ __forceinline__ void mma16816(float* c, const uint32_t* a, const uint32_t* b) {
    asm volatile(
        "mma.sync.aligned.m16n8k16.row.col.f32.bf16.bf16.f32 "
        "{%0,%1,%2,%3},{%4,%5,%6,%7},{%8,%9},{%0,%1,%2,%3};"
        : "+f"(c[0]), "+f"(c[1]), "+f"(c[2]), "+f"(c[3])
        : "r"(a[0]), "r"(a[1]), "r"(a[2]), "r"(a[3]), "r"(b[0]), "r"(b[1]));
}

__device__ __forceinline__ void cp16(uint32_t smem_addr, const void* gptr, int srcbytes) {
    asm volatile("cp.async.cg.shared.global [%0], [%1], 16, %2;"
                 :: "r"(smem_addr), "l"(gptr), "r"(srcbytes) : "memory");
}
#define CP_COMMIT() asm volatile("cp.async.commit_group;" ::: "memory")
#define CP_WAIT(n)  asm volatile("cp.async.wait_group %0;" :: "n"(n) : "memory")

// swizzled byte offset within a 128x32 bf16 tile (row stride 64B, 16B groups XORed)
__device__ __forceinline__ uint32_t swz(int row, int c16) {
    return (uint32_t)(row * 64) + (uint32_t)(((c16 ^ ((row >> 1) & 3)) << 4));
}

__device__ __forceinline__ void split1(float v, __nv_bfloat16& h, __nv_bfloat16& l) {
    h = __float2bfloat16(v);
    l = __float2bfloat16(v - __bfloat162float(h));
}

// ---- one K=32 chunk of split-bf16 MMA. A tile at Abase {hi,+8192 lo};
// ---- NB n-blocks at Bbase + nb*16384 {hi,+8192 lo}.
template<int NB>
__device__ __forceinline__ void chunk_mma(uint32_t Abase, uint32_t Bbase,
                                          int mo, int no, int lid,
                                          float acc[NB][4][4][4])
{
    const int lrow = lid & 15;
    const int lc = lid >> 4;
#pragma unroll
    for (int ks = 0; ks < 2; ++ks) {
        const int cA = (ks << 1) + lc;
        uint32_t afh[4][4], afl[4][4];
#pragma unroll
        for (int i = 0; i < 4; ++i) {
            const int row = mo + i * 16 + lrow;
            const uint32_t so = swz(row, cA);
            ldmx4(afh[i], Abase + so);
            ldmx4(afl[i], Abase + 8192u + so);
        }
#pragma unroll
        for (int nb = 0; nb < NB; ++nb) {
            uint32_t bfh[4][2], bfl[4][2];
#pragma unroll
            for (int jj = 0; jj < 2; ++jj) {
                const int row = no + jj * 16 + lrow;
                const uint32_t so = swz(row, cA) + (uint32_t)nb * 16384u;
                uint32_t r4[4];
                ldmx4(r4, Bbase + so);
                bfh[jj * 2 + 0][0] = r4[0]; bfh[jj * 2 + 0][1] = r4[2];
                bfh[jj * 2 + 1][0] = r4[1]; bfh[jj * 2 + 1][1] = r4[3];
                ldmx4(r4, Bbase + 8192u + so);
                bfl[jj * 2 + 0][0] = r4[0]; bfl[jj * 2 + 0][1] = r4[2];
                bfl[jj * 2 + 1][0] = r4[1]; bfl[jj * 2 + 1][1] = r4[3];
            }
#pragma unroll
            for (int i = 0; i < 4; ++i)
#pragma unroll
                for (int j = 0; j < 4; ++j) {
                    mma16816(acc[nb][i][j], afh[i], bfh[j]);
                    mma16816(acc[nb][i][j], afh[i], bfl[j]);
                    mma16816(acc[nb][i][j], afl[i], bfh[j]);
                }
        }
    }
}

// ---- epilogue into act smem: bias + leaky-relu + bf16 split, swizzled layout ----
template<int NB>
__device__ __forceinline__ void epi_to_act(float acc[NB][4][4][4], const float* bias,
                                           uint32_t act, int mo, int no, int lid)
{
    const int g = lid >> 2;
    const int t2c = (lid & 3) << 1;
#pragma unroll
    for (int nb = 0; nb < NB; ++nb)
#pragma unroll
    for (int i = 0; i < 4; ++i) {
        const int row0 = mo + i * 16 + g;
#pragma unroll
        for (int j = 0; j < 4; ++j) {
            const int col = nb * 128 + no + j * 8 + t2c;
            const float2 bv = *(const float2*)(bias + col);
            const uint32_t cbase = act + (uint32_t)(col >> 5) * 16384u;
            const int c16 = (col & 31) >> 3;
            const uint32_t sub = (uint32_t)((col & 7) << 1);
#pragma unroll
            for (int h = 0; h < 2; ++h) {
                const int row = row0 + h * 8;
                float ox = acc[nb][i][j][h * 2 + 0] + bv.x;
                float oy = acc[nb][i][j][h * 2 + 1] + bv.y;
                ox = ox >= 0.f ? ox : 0.01f * ox;
                oy = oy >= 0.f ? oy : 0.01f * oy;
                __nv_bfloat16 hx, lx, hy, ly;
                split1(ox, hx, lx);
                split1(oy, hy, ly);
                uint32_t hp = (uint32_t)__bfloat16_as_ushort(hx) | ((uint32_t)__bfloat16_as_ushort(hy) << 16);
                uint32_t lp = (uint32_t)__bfloat16_as_ushort(lx) | ((uint32_t)__bfloat16_as_ushort(ly) << 16);
                const uint32_t ad = cbase + swz(row, c16) + sub;
                asm volatile("st.shared.b32 [%0], %1;" :: "r"(ad), "r"(hp) : "memory");
                asm volatile("st.shared.b32 [%0], %1;" :: "r"(ad + 8192u), "r"(lp) : "memory");
            }
        }
    }
}

// ---------------- fused MLP3 (fp32 in / fp32 out) --------------------------------
// A fp32 [Nr,128] split in-kernel; W1[256][128], W2[256][256], W3[128][256] hi/lo.
// ACT smem holds split A (slots 0-3), then layer1 out (slots 0-7), then layer2 out.
__global__ __launch_bounds__(256, 1)
void fused_mlp3(const float* __restrict__ Ag,
                const __nv_bfloat16* __restrict__ W1h, const __nv_bfloat16* __restrict__ W1l,
                const __nv_bfloat16* __restrict__ W2h, const __nv_bfloat16* __restrict__ W2l,
                const __nv_bfloat16* __restrict__ W3h, const __nv_bfloat16* __restrict__ W3l,
                const float* __restrict__ b1, const float* __restrict__ b2,
                const float* __restrict__ b3,
                float* __restrict__ Cf, int Nrows)
{
    extern __shared__ char smem[];
    const uint32_t sb = smem_to_u32(smem);
    const uint32_t ACT = sb;                 // 128KB: chunk c at +c*16384 {hi, +8192 lo}
    const uint32_t STG = sb + 131072u;       // 96KB: 3 stages x 32KB

    const int tid = threadIdx.x;
    const int wid = tid >> 5;
    const int lid = tid & 31;
    const int bm = blockIdx.x * 128;
    const int mo = (wid >> 2) * 64;
    const int no = (wid & 3) * 32;

    // B-stage issuer: `iters` x 256 cp16 ops; reg = (nb,hi/lo) pair index
    auto issueB = [&](const __nv_bfloat16* Wh, const __nv_bfloat16* Wl,
                      int kstride, int c, int iters) {
        const int k0 = c << 5;
        const uint32_t st = STG + (uint32_t)(c % 3) * 32768u;
        for (int it = 0; it < iters; ++it) {
            const int q = it * 256 + tid;
            const int reg = q >> 9;
            const int w = q & 511;
            const int row = w >> 2;
            const int c16 = w & 3;
            const int nb = reg >> 1;
            const __nv_bfloat16* base = (reg & 1) ? Wl : Wh;
            const __nv_bfloat16* src = base + (size_t)(nb * 128 + row) * kstride + k0 + (c16 << 3);
            cp16(st + (uint32_t)reg * 8192u + swz(row, c16), src, 16);
        }
        CP_COMMIT();
    };

    float acc[2][4][4][4];

    // ================= layer 1: K=128 (4 chunks) =================
    issueB(W1h, W1l, 128, 0, 8);
    issueB(W1h, W1l, 128, 1, 8);

    // A preload: fp32 -> split bf16 hi/lo -> ACT slots 0..3 (swizzled)
    {
        const int arow = tid >> 1;
        const int acol0 = (tid & 1) << 6;
        const int grow = bm + arow;
        const float* arp = Ag + (size_t)grow * 128 + acol0;
#pragma unroll
        for (int i = 0; i < 16; ++i) {
            const int col = acol0 + i * 4;
            float4 v = (grow < Nrows) ? *(const float4*)(arp + i * 4)
                                      : make_float4(0.f, 0.f, 0.f, 0.f);
            __nv_bfloat16 h0, l0, h1, l1, h2, l2, h3, l3;
            split1(v.x, h0, l0); split1(v.y, h1, l1);
            split1(v.z, h2, l2); split1(v.w, h3, l3);
            uint2 hp = make_uint2((uint32_t)__bfloat16_as_ushort(h0) | ((uint32_t)__bfloat16_as_ushort(h1) << 16),
                                  (uint32_t)__bfloat16_as_ushort(h2) | ((uint32_t)__bfloat16_as_ushort(h3) << 16));
            uint2 lp = make_uint2((uint32_t)__bfloat16_as_ushort(l0) | ((uint32_t)__bfloat16_as_ushort(l1) << 16),
                                  (uint32_t)__bfloat16_as_ushort(l2) | ((uint32_t)__bfloat16_as_ushort(l3) << 16));
            const uint32_t off = (uint32_t)(col >> 5) * 16384u
                               + swz(arow, (col & 31) >> 3) + ((col & 4) ? 8u : 0u);
            *(uint2*)(smem + off) = hp;
            *(uint2*)(smem + off + 8192u) = lp;
        }
    }

#pragma unroll
    for (int nb = 0; nb < 2; ++nb)
#pragma unroll
        for (int i = 0; i < 4; ++i)
#pragma unroll
            for (int j = 0; j < 4; ++j)
#pragma unroll
                for (int q = 0; q < 4; ++q) acc[nb][i][j][q] = 0.f;

    for (int c = 0; c < 4; ++c) {
        if (c < 3) { CP_WAIT(1); } else { CP_WAIT(0); }
        __syncthreads();                       // stage c ready; all warps past mma(c-1)
        if (c + 2 < 4) issueB(W1h, W1l, 128, c + 2, 8);
        chunk_mma<2>(ACT + (uint32_t)c * 16384u, STG + (uint32_t)(c % 3) * 32768u,
                     mo, no, lid, acc);
    }
    __syncthreads();                           // all A reads done before epi overwrite
    issueB(W2h, W2l, 256, 0, 8);               // overlap layer-2 prefetch with epilogue
    issueB(W2h, W2l, 256, 1, 8);
    epi_to_act<2>(acc, b1, ACT, mo, no, lid);

    // ================= layer 2: K=256 (8 chunks) =================
#pragma unroll
    for (int nb = 0; nb < 2; ++nb)
#pragma unroll
        for (int i = 0; i < 4; ++i)
#pragma unroll
            for (int j = 0; j < 4; ++j)
#pragma unroll
                for (int q = 0; q < 4; ++q) acc[nb][i][j][q] = 0.f;

    for (int c = 0; c < 8; ++c) {
        if (c < 7) { CP_WAIT(1); } else { CP_WAIT(0); }
        __syncthreads();
        if (c + 2 < 8) issueB(W2h, W2l, 256, c + 2, 8);
        chunk_mma<2>(ACT + (uint32_t)c * 16384u, STG + (uint32_t)(c % 3) * 32768u,
                     mo, no, lid, acc);
    }
    __syncthreads();
    issueB(W3h, W3l, 256, 0, 4);
    issueB(W3h, W3l, 256, 1, 4);
    epi_to_act<2>(acc, b2, ACT, mo, no, lid);

    // ================= layer 3: K=256 (8 chunks), M=128 =================
    float (&acc1)[1][4][4][4] = *reinterpret_cast<float(*)[1][4][4][4]>(acc);
#pragma unroll
    for (int i = 0; i < 4; ++i)
#pragma unroll
        for (int j = 0; j < 4; ++j)
#pragma unroll
            for (int q = 0; q < 4; ++q) acc1[0][i][j][q] = 0.f;

    for (int c = 0; c < 8; ++c) {
        if (c < 7) { CP_WAIT(1); } else { CP_WAIT(0); }
        __syncthreads();
        if (c + 2 < 8) issueB(W3h, W3l, 256, c + 2, 4);
        chunk_mma<1>(ACT + (uint32_t)c * 16384u, STG + (uint32_t)(c % 3) * 32768u,
                     mo, no, lid, acc1);
    }

    // ---- final epilogue: bias + leaky-relu, fp32 global stores ----
    {
        const int g = lid >> 2;
        const int t2c = (lid & 3) << 1;
#pragma unroll
        for (int i = 0; i < 4; ++i) {
            const int row0 = bm + mo + i * 16 + g;
#pragma unroll
            for (int j = 0; j < 4; ++j) {
                const int col = no + j * 8 + t2c;
                const float2 bv = *(const float2*)(b3 + col);
#pragma unroll
                for (int h = 0; h < 2; ++h) {
                    const int row = row0 + h * 8;
                    if (row >= Nrows) continue;
                    float2 o;
                    o.x = acc1[0][i][j][h * 2 + 0] + bv.x;
                    o.y = acc1[0][i][j][h * 2 + 1] + bv.y;
                    o.x = o.x >= 0.f ? o.x : 0.01f * o.x;
                    o.y = o.y >= 0.f ? o.y : 0.01f * o.y;
                    *(float2*)(Cf + (size_t)row * 128 + col) = o;
                }
            }
        }
    }
}

// ---------------- weight prep: all 6 matrices, one launch ----------------
__global__ void prep_all(const float* __restrict__ h1, const float* __restrict__ h2,
                         const float* __restrict__ h3, const float* __restrict__ f1,
                         const float* __restrict__ f2, const float* __restrict__ f3,
                         __nv_bfloat16* __restrict__ hi, __nv_bfloat16* __restrict__ lo)
{
    int idx = blockIdx.x * blockDim.x + threadIdx.x;
    if (idx >= 262144) return;
    const float* W; int K, M, off, li;
    if      (idx <  32768) { W = h1; K = 128; M = 256; off = 0;      li = idx; }
    else if (idx <  98304) { W = h2; K = 256; M = 256; off = 32768;  li = idx - 32768; }
    else if (idx < 131072) { W = h3; K = 256; M = 128; off = 98304;  li = idx - 98304; }
    else if (idx < 163840) { W = f1; K = 128; M = 256; off = 131072; li = idx - 131072; }
    else if (idx < 229376) { W = f2; K = 256; M = 256; off = 163840; li = idx - 163840; }
    else                   { W = f3; K = 256; M = 128; off = 229376; li = idx - 229376; }
    int k = li / M, m = li - k * M;
    float v = W[li];
    __nv_bfloat16 h, l;
    split1(v, h, l);
    hi[off + (size_t)m * K + k] = h;
    lo[off + (size_t)m * K + k] = l;
}

// ---------------- zero / scatter / residual ----------------
__global__ void zero_kernel(float4* __restrict__ p, int n4)
{
    int i = blockIdx.x * blockDim.x + threadIdx.x;
    if (i < n4) p[i] = make_float4(0.f, 0.f, 0.f, 0.f);
}

// one thread per (edge, 4 dims): 32 threads/edge; vectorized red.global.add.v4
__global__ void scatter_kernel(const int* __restrict__ src, const int* __restrict__ dst,
                               const float* __restrict__ vals,
                               const float* __restrict__ y, float* __restrict__ out,
                               int E)
{
    int gid = blockIdx.x * blockDim.x + threadIdx.x;
    int e = gid >> 5;
    int d4 = (gid & 31) << 2;
    if (e >= E) return;
    float v = vals[e];
    int srow = src[e];
    int t = dst[e];
    float4 yv = *(const float4*)(y + (size_t)t * 128 + d4);
    const float* o = out + (size_t)srow * 128 + d4;
    asm volatile("red.global.add.v4.f32 [%0], {%1,%2,%3,%4};"
                 :: "l"(o), "f"(v * yv.x), "f"(v * yv.y), "f"(v * yv.z), "f"(v * yv.w)
                 : "memory");
}

// x += mask*y (float4)
__global__ void residual_kernel(float* __restrict__ x, const float* __restrict__ y,
                                const float* __restrict__ mask, int n4)
{
    int i = blockIdx.x * blockDim.x + threadIdx.x;
    if (i >= n4) return;
    float m = mask[i >> 5];
    float4 xv = ((const float4*)x)[i];
    float4 yv = ((const float4*)y)[i];
    xv.x += m * yv.x; xv.y += m * yv.y; xv.z += m * yv.z; xv.w += m * yv.w;
    ((float4*)x)[i] = xv;
}

// ---------------- host orchestration ----------------
static const int FUSED_SMEM = 131072 + 98304;   // act 128KB + stages 96KB = 224KB

extern "C" void kernel_launch(void* const* d_in, const int* in_sizes, int n_in,
                              void* d_out, int out_size)
{
    const float* node_inputs = (const float*)d_in[0];
    const int*   edge_src    = (const int*)  d_in[1];
    const int*   edge_dst    = (const int*)  d_in[2];
    const float* adj_vals    = (const float*)d_in[3];
    const float* masks       = (const float*)d_in[4];
    const float* W_h1 = (const float*)d_in[5];
    const float* b_h1 = (const float*)d_in[6];
    const float* W_h2 = (const float*)d_in[7];
    const float* b_h2 = (const float*)d_in[8];
    const float* W_h3 = (const float*)d_in[9];
    const float* b_h3 = (const float*)d_in[10];
    const float* W_f1 = (const float*)d_in[11];
    const float* b_f1 = (const float*)d_in[12];
    const float* W_f2 = (const float*)d_in[13];
    const float* b_f2 = (const float*)d_in[14];
    const float* W_f3 = (const float*)d_in[15];
    const float* b_f3 = (const float*)d_in[16];

    float* x = (float*)d_out;

    float *y, *s;
    __nv_bfloat16 *whi, *wlo;
    cudaGetSymbolAddress((void**)&y,   g_y);
    cudaGetSymbolAddress((void**)&s,   g_s);
    cudaGetSymbolAddress((void**)&whi, g_wt_hi);
    cudaGetSymbolAddress((void**)&wlo, g_wt_lo);

    cudaFuncSetAttribute(fused_mlp3, cudaFuncAttributeMaxDynamicSharedMemorySize, FUSED_SMEM);

    // packed offsets for the 6 transposed/split weight matrices
    const int OH1 = 0, OH2 = 32768, OH3 = 98304, OF1 = 131072, OF2 = 163840, OF3 = 229376;

    prep_all<<<262144 / 256, 256>>>(W_h1, W_h2, W_h3, W_f1, W_f2, W_f3, whi, wlo);

    const int NE = NN * 128;
    const int NE4 = NE / 4;
    const int GRID = (NN + 127) / 128;   // 391

    // embedding MLP: x = mlp3(node_inputs; W_h*)
    fused_mlp3<<<GRID, 256, FUSED_SMEM>>>(node_inputs,
        whi + OH1, wlo + OH1, whi + OH2, wlo + OH2, whi + OH3, wlo + OH3,
        b_h1, b_h2, b_h3, x, NN);

    for (int d = 0; d < DEPTH; d++) {
        // y = mlp3(x)
        fused_mlp3<<<GRID, 256, FUSED_SMEM>>>(x,
            whi + OF1, wlo + OF1, whi + OF2, wlo + OF2, whi + OF3, wlo + OF3,
            b_f1, b_f2, b_f3, y, NN);

        // s = segment_sum(adj_vals * y[dst], src)
        zero_kernel<<<(NE4 + 255) / 256, 256>>>((float4*)s, NE4);
        {
            long long tot = (long long)EE * 32;
            int blocks = (int)((tot + 255) / 256);
            scatter_kernel<<<blocks, 256>>>(edge_src + (size_t)d * EE,
                                            edge_dst + (size_t)d * EE,
                                            adj_vals + (size_t)d * EE,
                                            y, s, EE);
        }

        // y = mlp3(s)
        fused_mlp3<<<GRID, 256, FUSED_SMEM>>>(s,
            whi + OF1, wlo + OF1, whi + OF2, wlo + OF2, whi + OF3, wlo + OF3,
            b_f1, b_f2, b_f3, y, NN);

        // x += mask[d] * y
        residual_kernel<<<(NE4 + 255) / 256, 256>>>(x, y, masks + (size_t)d * NN, NE4);
    }
}

// round 7
// speedup vs baseline: 2.6672x; 1.0265x over previous
#include <cuda_runtime.h>
#include <cuda_bf16.h>
#include <cstdint>

#define NN 50000
#define EE 600000
#define DEPTH 8

// ---------------- scratch (alloc-free rule: __device__ globals) ----------------
__device__ __align__(16) float g_y[NN * 128];
__device__ __align__(16) float g_s[NN * 128];
// transposed + bf16-split weights: [M][K] layout, 6 matrices packed
__device__ __align__(16) __nv_bfloat16 g_wt_hi[262144];
__device__ __align__(16) __nv_bfloat16 g_wt_lo[262144];
// CSR per depth
__device__ int   g_cnt[DEPTH * NN];
__device__ int   g_cur[DEPTH * NN];
__device__ int   g_rp [DEPTH * (NN + 1)];
__device__ int   g_col[DEPTH * EE];
__device__ float g_val[DEPTH * EE];

// ---------------- helpers ----------------
__device__ __forceinline__ uint32_t smem_to_u32(const void* smem_ptr) {
    uint32_t addr;
    asm("{ .reg .u64 tmp; cvta.to.shared.u64 tmp, %1; cvt.u32.u64 %0, tmp; }"
        : "=r"(addr) : "l"(smem_ptr));
    return addr;
}

__device__ __forceinline__ void ldmx4(uint32_t* d, uint32_t addr) {
    asm volatile("ldmatrix.sync.aligned.m8n8.x4.shared.b16 {%0,%1,%2,%3}, [%4];"
                 : "=r"(d[0]), "=r"(d[1]), "=r"(d[2]), "=r"(d[3]) : "r"(addr));
}

__device__ __forceinline__ void mma16816(float* c, const uint32_t* a, const uint32_t* b) {
    asm volatile(
        "mma.sync.aligned.m16n8k16.row.col.f32.bf16.bf16.f32 "
        "{%0,%1,%2,%3},{%4,%5,%6,%7},{%8,%9},{%0,%1,%2,%3};"
        : "+f"(c[0]), "+f"(c[1]), "+f"(c[2]), "+f"(c[3])
        : "r"(a[0]), "r"(a[1]), "r"(a[2]), "r"(a[3]), "r"(b[0]), "r"(b[1]));
}

__device__ __forceinline__ void cp16(uint32_t smem_addr, const void* gptr, int srcbytes) {
    asm volatile("cp.async.cg.shared.global [%0], [%1], 16, %2;"
                 :: "r"(smem_addr), "l"(gptr), "r"(srcbytes) : "memory");
}
#define CP_COMMIT() asm volatile("cp.async.commit_group;" ::: "memory")
#define CP_WAIT(n)  asm volatile("cp.async.wait_group %0;" :: "n"(n) : "memory")

// swizzled byte offset within a 128x32 bf16 tile (row stride 64B, 16B groups XORed)
__device__ __forceinline__ uint32_t swz(int row, int c16) {
    return (uint32_t)(row * 64) + (uint32_t)(((c16 ^ ((row >> 1) & 3)) << 4));
}

__device__ __forceinline__ void split1(float v, __nv_bfloat16& h, __nv_bfloat16& l) {
    h = __float2bfloat16(v);
    l = __float2bfloat16(v - __bfloat162float(h));
}

// ---- one K=32 chunk of split-bf16 MMA. A tile at Abase {hi,+8192 lo};
// ---- NB n-blocks at Bbase + nb*16384 {hi,+8192 lo}.
template<int NB>
__device__ __forceinline__ void chunk_mma(uint32_t Abase, uint32_t Bbase,
                                          int mo, int no, int lid,
                                          float acc[NB][4][4][4])
{
    const int lrow = lid & 15;
    const int lc = lid >> 4;
#pragma unroll
    for (int ks = 0; ks < 2; ++ks) {
        const int cA = (ks << 1) + lc;
        uint32_t afh[4][4], afl[4][4];
#pragma unroll
        for (int i = 0; i < 4; ++i) {
            const int row = mo + i * 16 + lrow;
            const uint32_t so = swz(row, cA);
            ldmx4(afh[i], Abase + so);
            ldmx4(afl[i], Abase + 8192u + so);
        }
#pragma unroll
        for (int nb = 0; nb < NB; ++nb) {
            uint32_t bfh[4][2], bfl[4][2];
#pragma unroll
            for (int jj = 0; jj < 2; ++jj) {
                const int row = no + jj * 16 + lrow;
                const uint32_t so = swz(row, cA) + (uint32_t)nb * 16384u;
                uint32_t r4[4];
                ldmx4(r4, Bbase + so);
                bfh[jj * 2 + 0][0] = r4[0]; bfh[jj * 2 + 0][1] = r4[2];
                bfh[jj * 2 + 1][0] = r4[1]; bfh[jj * 2 + 1][1] = r4[3];
                ldmx4(r4, Bbase + 8192u + so);
                bfl[jj * 2 + 0][0] = r4[0]; bfl[jj * 2 + 0][1] = r4[2];
                bfl[jj * 2 + 1][0] = r4[1]; bfl[jj * 2 + 1][1] = r4[3];
            }
#pragma unroll
            for (int i = 0; i < 4; ++i)
#pragma unroll
                for (int j = 0; j < 4; ++j) {
                    mma16816(acc[nb][i][j], afh[i], bfh[j]);
                    mma16816(acc[nb][i][j], afh[i], bfl[j]);
                    mma16816(acc[nb][i][j], afl[i], bfh[j]);
                }
        }
    }
}

// ---- epilogue into act smem: bias + leaky-relu + bf16 split, swizzled layout ----
template<int NB>
__device__ __forceinline__ void epi_to_act(float acc[NB][4][4][4], const float* bias,
                                           uint32_t act, int mo, int no, int lid)
{
    const int g = lid >> 2;
    const int t2c = (lid & 3) << 1;
#pragma unroll
    for (int nb = 0; nb < NB; ++nb)
#pragma unroll
    for (int i = 0; i < 4; ++i) {
        const int row0 = mo + i * 16 + g;
#pragma unroll
        for (int j = 0; j < 4; ++j) {
            const int col = nb * 128 + no + j * 8 + t2c;
            const float2 bv = *(const float2*)(bias + col);
            const uint32_t cbase = act + (uint32_t)(col >> 5) * 16384u;
            const int c16 = (col & 31) >> 3;
            const uint32_t sub = (uint32_t)((col & 7) << 1);
#pragma unroll
            for (int h = 0; h < 2; ++h) {
                const int row = row0 + h * 8;
                float ox = acc[nb][i][j][h * 2 + 0] + bv.x;
                float oy = acc[nb][i][j][h * 2 + 1] + bv.y;
                ox = ox >= 0.f ? ox : 0.01f * ox;
                oy = oy >= 0.f ? oy : 0.01f * oy;
                __nv_bfloat16 hx, lx, hy, ly;
                split1(ox, hx, lx);
                split1(oy, hy, ly);
                uint32_t hp = (uint32_t)__bfloat16_as_ushort(hx) | ((uint32_t)__bfloat16_as_ushort(hy) << 16);
                uint32_t lp = (uint32_t)__bfloat16_as_ushort(lx) | ((uint32_t)__bfloat16_as_ushort(ly) << 16);
                const uint32_t ad = cbase + swz(row, c16) + sub;
                asm volatile("st.shared.b32 [%0], %1;" :: "r"(ad), "r"(hp) : "memory");
                asm volatile("st.shared.b32 [%0], %1;" :: "r"(ad + 8192u), "r"(lp) : "memory");
            }
        }
    }
}

// ---------------- fused MLP3 (fp32 in / fp32 out, optional masked residual) ------
// out = lrelu(mlp3(A)); if xin: Cf = xin + mask*out  else Cf = out
__global__ __launch_bounds__(256, 1)
void fused_mlp3(const float* __restrict__ Ag,
                const __nv_bfloat16* __restrict__ W1h, const __nv_bfloat16* __restrict__ W1l,
                const __nv_bfloat16* __restrict__ W2h, const __nv_bfloat16* __restrict__ W2l,
                const __nv_bfloat16* __restrict__ W3h, const __nv_bfloat16* __restrict__ W3l,
                const float* __restrict__ b1, const float* __restrict__ b2,
                const float* __restrict__ b3,
                float* __restrict__ Cf, const float* __restrict__ xin,
                const float* __restrict__ maskp, int Nrows)
{
    extern __shared__ char smem[];
    const uint32_t sb = smem_to_u32(smem);
    const uint32_t ACT = sb;                 // 128KB: chunk c at +c*16384 {hi, +8192 lo}
    const uint32_t STG = sb + 131072u;       // 96KB: 3 stages x 32KB

    const int tid = threadIdx.x;
    const int wid = tid >> 5;
    const int lid = tid & 31;
    const int bm = blockIdx.x * 128;
    const int mo = (wid >> 2) * 64;
    const int no = (wid & 3) * 32;

    auto issueB = [&](const __nv_bfloat16* Wh, const __nv_bfloat16* Wl,
                      int kstride, int c, int iters) {
        const int k0 = c << 5;
        const uint32_t st = STG + (uint32_t)(c % 3) * 32768u;
        for (int it = 0; it < iters; ++it) {
            const int q = it * 256 + tid;
            const int reg = q >> 9;
            const int w = q & 511;
            const int row = w >> 2;
            const int c16 = w & 3;
            const int nb = reg >> 1;
            const __nv_bfloat16* base = (reg & 1) ? Wl : Wh;
            const __nv_bfloat16* src = base + (size_t)(nb * 128 + row) * kstride + k0 + (c16 << 3);
            cp16(st + (uint32_t)reg * 8192u + swz(row, c16), src, 16);
        }
        CP_COMMIT();
    };

    float acc[2][4][4][4];

    // ================= layer 1: K=128 (4 chunks) =================
    issueB(W1h, W1l, 128, 0, 8);
    issueB(W1h, W1l, 128, 1, 8);

    // A preload: fp32 -> split bf16 hi/lo -> ACT slots 0..3 (swizzled)
    {
        const int arow = tid >> 1;
        const int acol0 = (tid & 1) << 6;
        const int grow = bm + arow;
        const float* arp = Ag + (size_t)grow * 128 + acol0;
#pragma unroll
        for (int i = 0; i < 16; ++i) {
            const int col = acol0 + i * 4;
            float4 v = (grow < Nrows) ? *(const float4*)(arp + i * 4)
                                      : make_float4(0.f, 0.f, 0.f, 0.f);
            __nv_bfloat16 h0, l0, h1, l1, h2, l2, h3, l3;
            split1(v.x, h0, l0); split1(v.y, h1, l1);
            split1(v.z, h2, l2); split1(v.w, h3, l3);
            uint2 hp = make_uint2((uint32_t)__bfloat16_as_ushort(h0) | ((uint32_t)__bfloat16_as_ushort(h1) << 16),
                                  (uint32_t)__bfloat16_as_ushort(h2) | ((uint32_t)__bfloat16_as_ushort(h3) << 16));
            uint2 lp = make_uint2((uint32_t)__bfloat16_as_ushort(l0) | ((uint32_t)__bfloat16_as_ushort(l1) << 16),
                                  (uint32_t)__bfloat16_as_ushort(l2) | ((uint32_t)__bfloat16_as_ushort(l3) << 16));
            const uint32_t off = (uint32_t)(col >> 5) * 16384u
                               + swz(arow, (col & 31) >> 3) + ((col & 4) ? 8u : 0u);
            *(uint2*)(smem + off) = hp;
            *(uint2*)(smem + off + 8192u) = lp;
        }
    }

#pragma unroll
    for (int nb = 0; nb < 2; ++nb)
#pragma unroll
        for (int i = 0; i < 4; ++i)
#pragma unroll
            for (int j = 0; j < 4; ++j)
#pragma unroll
                for (int q = 0; q < 4; ++q) acc[nb][i][j][q] = 0.f;

    for (int c = 0; c < 4; ++c) {
        if (c < 3) { CP_WAIT(1); } else { CP_WAIT(0); }
        __syncthreads();
        if (c + 2 < 4) issueB(W1h, W1l, 128, c + 2, 8);
        chunk_mma<2>(ACT + (uint32_t)c * 16384u, STG + (uint32_t)(c % 3) * 32768u,
                     mo, no, lid, acc);
    }
    __syncthreads();
    issueB(W2h, W2l, 256, 0, 8);
    issueB(W2h, W2l, 256, 1, 8);
    epi_to_act<2>(acc, b1, ACT, mo, no, lid);

    // ================= layer 2: K=256 (8 chunks) =================
#pragma unroll
    for (int nb = 0; nb < 2; ++nb)
#pragma unroll
        for (int i = 0; i < 4; ++i)
#pragma unroll
            for (int j = 0; j < 4; ++j)
#pragma unroll
                for (int q = 0; q < 4; ++q) acc[nb][i][j][q] = 0.f;

    for (int c = 0; c < 8; ++c) {
        if (c < 7) { CP_WAIT(1); } else { CP_WAIT(0); }
        __syncthreads();
        if (c + 2 < 8) issueB(W2h, W2l, 256, c + 2, 8);
        chunk_mma<2>(ACT + (uint32_t)c * 16384u, STG + (uint32_t)(c % 3) * 32768u,
                     mo, no, lid, acc);
    }
    __syncthreads();
    issueB(W3h, W3l, 256, 0, 4);
    issueB(W3h, W3l, 256, 1, 4);
    epi_to_act<2>(acc, b2, ACT, mo, no, lid);

    // ================= layer 3: K=256 (8 chunks), M=128 =================
    float (&acc1)[1][4][4][4] = *reinterpret_cast<float(*)[1][4][4][4]>(acc);
#pragma unroll
    for (int i = 0; i < 4; ++i)
#pragma unroll
        for (int j = 0; j < 4; ++j)
#pragma unroll
            for (int q = 0; q < 4; ++q) acc1[0][i][j][q] = 0.f;

    for (int c = 0; c < 8; ++c) {
        if (c < 7) { CP_WAIT(1); } else { CP_WAIT(0); }
        __syncthreads();
        if (c + 2 < 8) issueB(W3h, W3l, 256, c + 2, 4);
        chunk_mma<1>(ACT + (uint32_t)c * 16384u, STG + (uint32_t)(c % 3) * 32768u,
                     mo, no, lid, acc1);
    }

    // ---- final epilogue: bias + leaky-relu (+ optional masked residual) ----
    {
        const int g = lid >> 2;
        const int t2c = (lid & 3) << 1;
#pragma unroll
        for (int i = 0; i < 4; ++i) {
            const int row0 = bm + mo + i * 16 + g;
#pragma unroll
            for (int j = 0; j < 4; ++j) {
                const int col = no + j * 8 + t2c;
                const float2 bv = *(const float2*)(b3 + col);
#pragma unroll
                for (int h = 0; h < 2; ++h) {
                    const int row = row0 + h * 8;
                    if (row >= Nrows) continue;
                    float2 o;
                    o.x = acc1[0][i][j][h * 2 + 0] + bv.x;
                    o.y = acc1[0][i][j][h * 2 + 1] + bv.y;
                    o.x = o.x >= 0.f ? o.x : 0.01f * o.x;
                    o.y = o.y >= 0.f ? o.y : 0.01f * o.y;
                    const size_t off = (size_t)row * 128 + col;
                    if (xin) {
                        const float m = maskp[row];
                        const float2 xv = *(const float2*)(xin + off);
                        o.x = xv.x + m * o.x;
                        o.y = xv.y + m * o.y;
                    }
                    *(float2*)(Cf + off) = o;
                }
            }
        }
    }
}

// ---------------- weight prep: all 6 matrices, one launch ----------------
__global__ void prep_all(const float* __restrict__ h1, const float* __restrict__ h2,
                         const float* __restrict__ h3, const float* __restrict__ f1,
                         const float* __restrict__ f2, const float* __restrict__ f3,
                         __nv_bfloat16* __restrict__ hi, __nv_bfloat16* __restrict__ lo)
{
    int idx = blockIdx.x * blockDim.x + threadIdx.x;
    if (idx >= 262144) return;
    const float* W; int K, M, off, li;
    if      (idx <  32768) { W = h1; K = 128; M = 256; off = 0;      li = idx; }
    else if (idx <  98304) { W = h2; K = 256; M = 256; off = 32768;  li = idx - 32768; }
    else if (idx < 131072) { W = h3; K = 256; M = 128; off = 98304;  li = idx - 98304; }
    else if (idx < 163840) { W = f1; K = 128; M = 256; off = 131072; li = idx - 131072; }
    else if (idx < 229376) { W = f2; K = 256; M = 256; off = 163840; li = idx - 163840; }
    else                   { W = f3; K = 256; M = 128; off = 229376; li = idx - 229376; }
    int k = li / M, m = li - k * M;
    float v = W[li];
    __nv_bfloat16 h, l;
    split1(v, h, l);
    hi[off + (size_t)m * K + k] = h;
    lo[off + (size_t)m * K + k] = l;
}

// ---------------- CSR build ----------------
__global__ void zero_int(int* __restrict__ p, int n)
{
    int i = blockIdx.x * blockDim.x + threadIdx.x;
    if (i < n) p[i] = 0;
}

__global__ void hist_kernel(const int* __restrict__ src, int* __restrict__ cnt)
{
    int idx = blockIdx.x * blockDim.x + threadIdx.x;
    if (idx >= DEPTH * EE) return;
    int d = idx / EE;
    atomicAdd(&cnt[d * NN + src[idx]], 1);
}

// one CTA per depth; 1024 threads, 49 elements/thread
__global__ void scan_kernel(const int* __restrict__ cnt, int* __restrict__ rp)
{
    const int d = blockIdx.x;
    const int t = threadIdx.x;
    const int CH = 49;
    __shared__ int part[1024];
    const int base = t * CH;
    int sum = 0;
    for (int i = 0; i < CH; ++i) {
        int idx = base + i;
        if (idx < NN) sum += cnt[d * NN + idx];
    }
    part[t] = sum;
    __syncthreads();
    for (int off = 1; off < 1024; off <<= 1) {
        int v = (t >= off) ? part[t - off] : 0;
        __syncthreads();
        part[t] += v;
        __syncthreads();
    }
    int run = (t == 0) ? 0 : part[t - 1];
    for (int i = 0; i < CH; ++i) {
        int idx = base + i;
        if (idx < NN) {
            rp[d * (NN + 1) + idx] = run;
            run += cnt[d * NN + idx];
        }
    }
    if (t == 1023) rp[d * (NN + 1) + NN] = run;
}

__global__ void cursor_init(const int* __restrict__ rp, int* __restrict__ cur)
{
    int idx = blockIdx.x * blockDim.x + threadIdx.x;
    if (idx >= DEPTH * NN) return;
    int d = idx / NN, n = idx - d * NN;
    cur[idx] = rp[d * (NN + 1) + n];
}

__global__ void fill_kernel(const int* __restrict__ src, const int* __restrict__ dst,
                            const float* __restrict__ vals, int* __restrict__ cur,
                            int* __restrict__ col, float* __restrict__ val)
{
    int idx = blockIdx.x * blockDim.x + threadIdx.x;
    if (idx >= DEPTH * EE) return;
    int d = idx / EE;
    int pos = atomicAdd(&cur[d * NN + src[idx]], 1);
    col[(size_t)d * EE + pos] = dst[idx];
    val[(size_t)d * EE + pos] = vals[idx];
}

// ---------------- gather: s[n] = sum_{e in CSR[n]} val_e * y[col_e] --------------
// one warp per node; lane covers 4 dims (float4)
__global__ void gather_kernel(const int* __restrict__ rp, const int* __restrict__ col,
                              const float* __restrict__ val,
                              const float* __restrict__ y, float* __restrict__ out)
{
    int gid = blockIdx.x * blockDim.x + threadIdx.x;
    int node = gid >> 5;
    int lane = gid & 31;
    if (node >= NN) return;
    int beg = rp[node], end = rp[node + 1];
    float4 acc = make_float4(0.f, 0.f, 0.f, 0.f);
    for (int i = beg; i < end; ++i) {
        int dn = col[i];
        float v = val[i];
        float4 yv = ((const float4*)y)[(size_t)dn * 32 + lane];
        acc.x += v * yv.x; acc.y += v * yv.y;
        acc.z += v * yv.z; acc.w += v * yv.w;
    }
    ((float4*)out)[(size_t)node * 32 + lane] = acc;
}

// ---------------- host orchestration ----------------
static const int FUSED_SMEM = 131072 + 98304;   // act 128KB + stages 96KB = 224KB

extern "C" void kernel_launch(void* const* d_in, const int* in_sizes, int n_in,
                              void* d_out, int out_size)
{
    const float* node_inputs = (const float*)d_in[0];
    const int*   edge_src    = (const int*)  d_in[1];
    const int*   edge_dst    = (const int*)  d_in[2];
    const float* adj_vals    = (const float*)d_in[3];
    const float* masks       = (const float*)d_in[4];
    const float* W_h1 = (const float*)d_in[5];
    const float* b_h1 = (const float*)d_in[6];
    const float* W_h2 = (const float*)d_in[7];
    const float* b_h2 = (const float*)d_in[8];
    const float* W_h3 = (const float*)d_in[9];
    const float* b_h3 = (const float*)d_in[10];
    const float* W_f1 = (const float*)d_in[11];
    const float* b_f1 = (const float*)d_in[12];
    const float* W_f2 = (const float*)d_in[13];
    const float* b_f2 = (const float*)d_in[14];
    const float* W_f3 = (const float*)d_in[15];
    const float* b_f3 = (const float*)d_in[16];

    float* x = (float*)d_out;

    float *y, *s, *valp;
    __nv_bfloat16 *whi, *wlo;
    int *cnt, *cur, *rp, *colp;
    cudaGetSymbolAddress((void**)&y,    g_y);
    cudaGetSymbolAddress((void**)&s,    g_s);
    cudaGetSymbolAddress((void**)&whi,  g_wt_hi);
    cudaGetSymbolAddress((void**)&wlo,  g_wt_lo);
    cudaGetSymbolAddress((void**)&cnt,  g_cnt);
    cudaGetSymbolAddress((void**)&cur,  g_cur);
    cudaGetSymbolAddress((void**)&rp,   g_rp);
    cudaGetSymbolAddress((void**)&colp, g_col);
    cudaGetSymbolAddress((void**)&valp, g_val);

    cudaFuncSetAttribute(fused_mlp3, cudaFuncAttributeMaxDynamicSharedMemorySize, FUSED_SMEM);

    const int OH1 = 0, OH2 = 32768, OH3 = 98304, OF1 = 131072, OF2 = 163840, OF3 = 229376;

    // weight prep + CSR build (independent of x; once per call)
    prep_all<<<262144 / 256, 256>>>(W_h1, W_h2, W_h3, W_f1, W_f2, W_f3, whi, wlo);
    zero_int<<<(DEPTH * NN + 255) / 256, 256>>>(cnt, DEPTH * NN);
    hist_kernel<<<(DEPTH * EE + 255) / 256, 256>>>(edge_src, cnt);
    scan_kernel<<<DEPTH, 1024>>>(cnt, rp);
    cursor_init<<<(DEPTH * NN + 255) / 256, 256>>>(rp, cur);
    fill_kernel<<<(DEPTH * EE + 255) / 256, 256>>>(edge_src, edge_dst, adj_vals,
                                                   cur, colp, valp);

    const int GRID = (NN + 127) / 128;   // 391
    const int GATHER_BLOCKS = (NN * 32 + 255) / 256;

    // embedding MLP: x = mlp3(node_inputs; W_h*)
    fused_mlp3<<<GRID, 256, FUSED_SMEM>>>(node_inputs,
        whi + OH1, wlo + OH1, whi + OH2, wlo + OH2, whi + OH3, wlo + OH3,
        b_h1, b_h2, b_h3, x, nullptr, nullptr, NN);

    for (int d = 0; d < DEPTH; d++) {
        // y = mlp3(x)
        fused_mlp3<<<GRID, 256, FUSED_SMEM>>>(x,
            whi + OF1, wlo + OF1, whi + OF2, wlo + OF2, whi + OF3, wlo + OF3,
            b_f1, b_f2, b_f3, y, nullptr, nullptr, NN);

        // s = segment_sum(adj_vals * y[dst], src)  — CSR gather, no atomics
        gather_kernel<<<GATHER_BLOCKS, 256>>>(rp + d * (NN + 1),
                                              colp + (size_t)d * EE,
                                              valp + (size_t)d * EE, y, s);

        // x = x + mask[d] * mlp3(s)   (residual fused into epilogue)
        fused_mlp3<<<GRID, 256, FUSED_SMEM>>>(s,
            whi + OF1, wlo + OF1, whi + OF2, wlo + OF2, whi + OF3, wlo + OF3,
            b_f1, b_f2, b_f3, x, x, masks + (size_t)d * NN, NN);
    }
}

// round 8
// speedup vs baseline: 2.8537x; 1.0699x over previous
#include <cuda_runtime.h>
#include <cuda_bf16.h>
#include <cstdint>

#define NN 50000
#define EE 600000
#define DEPTH 8
#define NTHREADS 512

// ---------------- scratch (alloc-free rule: __device__ globals) ----------------
__device__ __align__(16) float g_y[NN * 128];
__device__ __align__(16) float g_s[NN * 128];
__device__ __align__(16) __nv_bfloat16 g_wt_hi[262144];
__device__ __align__(16) __nv_bfloat16 g_wt_lo[262144];
// CSR per depth
__device__ int   g_cnt[DEPTH * NN];
__device__ int   g_cur[DEPTH * NN];
__device__ int   g_rp [DEPTH * (NN + 1)];
__device__ int   g_col[DEPTH * EE];
__device__ float g_val[DEPTH * EE];

// ---------------- helpers ----------------
__device__ __forceinline__ uint32_t smem_to_u32(const void* smem_ptr) {
    uint32_t addr;
    asm("{ .reg .u64 tmp; cvta.to.shared.u64 tmp, %1; cvt.u32.u64 %0, tmp; }"
        : "=r"(addr) : "l"(smem_ptr));
    return addr;
}

__device__ __forceinline__ void ldmx4(uint32_t* d, uint32_t addr) {
    asm volatile("ldmatrix.sync.aligned.m8n8.x4.shared.b16 {%0,%1,%2,%3}, [%4];"
                 : "=r"(d[0]), "=r"(d[1]), "=r"(d[2]), "=r"(d[3]) : "r"(addr));
}

__device__ __forceinline__ void mma16816(float* c, const uint32_t* a, const uint32_t* b) {
    asm volatile(
        "mma.sync.aligned.m16n8k16.row.col.f32.bf16.bf16.f32 "
        "{%0,%1,%2,%3},{%4,%5,%6,%7},{%8,%9},{%0,%1,%2,%3};"
        : "+f"(c[0]), "+f"(c[1]), "+f"(c[2]), "+f"(c[3])
        : "r"(a[0]), "r"(a[1]), "r"(a[2]), "r"(a[3]), "r"(b[0]), "r"(b[1]));
}

__device__ __forceinline__ void cp16(uint32_t smem_addr, const void* gptr, int srcbytes) {
    asm volatile("cp.async.cg.shared.global [%0], [%1], 16, %2;"
                 :: "r"(smem_addr), "l"(gptr), "r"(srcbytes) : "memory");
}
#define CP_COMMIT() asm volatile("cp.async.commit_group;" ::: "memory")
#define CP_WAIT(n)  asm volatile("cp.async.wait_group %0;" :: "n"(n) : "memory")

// swizzled byte offset within a 128x32 bf16 tile (row stride 64B, 16B groups XORed)
__device__ __forceinline__ uint32_t swz(int row, int c16) {
    return (uint32_t)(row * 64) + (uint32_t)(((c16 ^ ((row >> 1) & 3)) << 4));
}

__device__ __forceinline__ void split1(float v, __nv_bfloat16& h, __nv_bfloat16& l) {
    h = __float2bfloat16(v);
    l = __float2bfloat16(v - __bfloat162float(h));
}

// ---- one K=32 chunk of split-bf16 MMA for one warp tile (MI m16-tiles x 32 cols).
// A tile at Abase {hi, +8192 lo}; B 32-col block rows at Bbase {hi, +8192 lo},
// row index = no + jj*16 + lane. B frags loaded first (reused across MI).
template<int MI>
__device__ __forceinline__ void chunk_mma(uint32_t Abase, uint32_t Bbase,
                                          int mo, int no, int lid,
                                          float acc[MI][4][4])
{
    const int lrow = lid & 15;
    const int lc = lid >> 4;
#pragma unroll
    for (int ks = 0; ks < 2; ++ks) {
        const int cA = (ks << 1) + lc;
        uint32_t bfh[4][2], bfl[4][2];
#pragma unroll
        for (int jj = 0; jj < 2; ++jj) {
            const int row = no + jj * 16 + lrow;
            const uint32_t so = swz(row, cA);
            uint32_t r4[4];
            ldmx4(r4, Bbase + so);
            bfh[jj * 2 + 0][0] = r4[0]; bfh[jj * 2 + 0][1] = r4[2];
            bfh[jj * 2 + 1][0] = r4[1]; bfh[jj * 2 + 1][1] = r4[3];
            ldmx4(r4, Bbase + 8192u + so);
            bfl[jj * 2 + 0][0] = r4[0]; bfl[jj * 2 + 0][1] = r4[2];
            bfl[jj * 2 + 1][0] = r4[1]; bfl[jj * 2 + 1][1] = r4[3];
        }
#pragma unroll
        for (int i = 0; i < MI; ++i) {
            const int row = mo + i * 16 + lrow;
            const uint32_t so = swz(row, cA);
            uint32_t afh[4], afl[4];
            ldmx4(afh, Abase + so);
            ldmx4(afl, Abase + 8192u + so);
#pragma unroll
            for (int j = 0; j < 4; ++j) {
                mma16816(acc[i][j], afh, bfh[j]);
                mma16816(acc[i][j], afh, bfl[j]);
                mma16816(acc[i][j], afl, bfh[j]);
            }
        }
    }
}

// ---- epilogue into act smem: bias + leaky-relu + bf16 split; warp owns MI*16 rows
// ---- x 32 cols at (mo, no_g) where no_g is the GLOBAL column base (0..224).
template<int MI>
__device__ __forceinline__ void epi_to_act(float acc[MI][4][4], const float* bias,
                                           uint32_t act, int mo, int no_g, int lid)
{
    const int g = lid >> 2;
    const int t2c = (lid & 3) << 1;
#pragma unroll
    for (int i = 0; i < MI; ++i) {
        const int row0 = mo + i * 16 + g;
#pragma unroll
        for (int j = 0; j < 4; ++j) {
            const int col = no_g + j * 8 + t2c;
            const float2 bv = *(const float2*)(bias + col);
            const uint32_t cbase = act + (uint32_t)(col >> 5) * 16384u;
            const int c16 = (col & 31) >> 3;
            const uint32_t sub = (uint32_t)((col & 7) << 1);
#pragma unroll
            for (int h = 0; h < 2; ++h) {
                const int row = row0 + h * 8;
                float ox = acc[i][j][h * 2 + 0] + bv.x;
                float oy = acc[i][j][h * 2 + 1] + bv.y;
                ox = ox >= 0.f ? ox : 0.01f * ox;
                oy = oy >= 0.f ? oy : 0.01f * oy;
                __nv_bfloat16 hx, lx, hy, ly;
                split1(ox, hx, lx);
                split1(oy, hy, ly);
                uint32_t hp = (uint32_t)__bfloat16_as_ushort(hx) | ((uint32_t)__bfloat16_as_ushort(hy) << 16);
                uint32_t lp = (uint32_t)__bfloat16_as_ushort(lx) | ((uint32_t)__bfloat16_as_ushort(ly) << 16);
                const uint32_t ad = cbase + swz(row, c16) + sub;
                asm volatile("st.shared.b32 [%0], %1;" :: "r"(ad), "r"(hp) : "memory");
                asm volatile("st.shared.b32 [%0], %1;" :: "r"(ad + 8192u), "r"(lp) : "memory");
            }
        }
    }
}

// ---------------- fused MLP3 (fp32 in / fp32 out, optional masked residual) ------
// 512 threads, 16 warps. l1/l2: warp grid 2(m)x8(n), tile 64x32. l3: 4x4, 32x32.
__global__ __launch_bounds__(NTHREADS, 1)
void fused_mlp3(const float* __restrict__ Ag,
                const __nv_bfloat16* __restrict__ W1h, const __nv_bfloat16* __restrict__ W1l,
                const __nv_bfloat16* __restrict__ W2h, const __nv_bfloat16* __restrict__ W2l,
                const __nv_bfloat16* __restrict__ W3h, const __nv_bfloat16* __restrict__ W3l,
                const float* __restrict__ b1, const float* __restrict__ b2,
                const float* __restrict__ b3,
                float* __restrict__ Cf, const float* __restrict__ xin,
                const float* __restrict__ maskp, int Nrows)
{
    extern __shared__ char smem[];
    const uint32_t sb = smem_to_u32(smem);
    const uint32_t ACT = sb;                 // 128KB: chunk c at +c*16384 {hi, +8192 lo}
    const uint32_t STG = sb + 131072u;       // 96KB stage region

    const int tid = threadIdx.x;
    const int wid = tid >> 5;
    const int lid = tid & 31;
    const int bm = blockIdx.x * 128;
    // layer 1/2 warp tile (64x32): 2 m-groups x 8 n-groups
    const int mo = (wid >> 3) * 64;
    const int no_g = (wid & 7) * 32;         // global col 0..224
    const int nb = no_g >> 7;                // which 128-col B block
    const int no_l = no_g & 127;             // row base within B block
    // layer 3 warp tile (32x32): 4 x 4
    const int mo3 = (wid >> 2) * 32;
    const int no3 = (wid & 3) * 32;

    // B-stage issuer: `iters` x 512 cp16 ops; reg = (nb,hi/lo) pair index
    auto issueB = [&](const __nv_bfloat16* Wh, const __nv_bfloat16* Wl,
                      int kstride, int c, int iters, int stgsz) {
        const int k0 = c << 5;
        const uint32_t st = STG + (uint32_t)(c % 3) * (uint32_t)stgsz;
        for (int it = 0; it < iters; ++it) {
            const int q = it * NTHREADS + tid;
            const int reg = q >> 9;
            const int w = q & 511;
            const int row = w >> 2;
            const int c16 = w & 3;
            const int blk = reg >> 1;
            const __nv_bfloat16* base = (reg & 1) ? Wl : Wh;
            const __nv_bfloat16* src = base + (size_t)(blk * 128 + row) * kstride + k0 + (c16 << 3);
            cp16(st + (uint32_t)reg * 8192u + swz(row, c16), src, 16);
        }
        CP_COMMIT();
    };

    float acc[4][4][4];

    // ================= layer 1: K=128 (4 chunks), 32KB stages =================
    issueB(W1h, W1l, 128, 0, 4, 32768);
    issueB(W1h, W1l, 128, 1, 4, 32768);

    // A preload: fp32 -> split bf16 hi/lo -> ACT slots 0..3 (swizzled)
    {
        const int arow = tid >> 2;
        const int acol0 = (tid & 3) << 5;
        const int grow = bm + arow;
        const float* arp = Ag + (size_t)grow * 128 + acol0;
#pragma unroll
        for (int i = 0; i < 8; ++i) {
            const int col = acol0 + i * 4;
            float4 v = (grow < Nrows) ? *(const float4*)(arp + i * 4)
                                      : make_float4(0.f, 0.f, 0.f, 0.f);
            __nv_bfloat16 h0, l0, h1, l1, h2, l2, h3, l3;
            split1(v.x, h0, l0); split1(v.y, h1, l1);
            split1(v.z, h2, l2); split1(v.w, h3, l3);
            uint2 hp = make_uint2((uint32_t)__bfloat16_as_ushort(h0) | ((uint32_t)__bfloat16_as_ushort(h1) << 16),
                                  (uint32_t)__bfloat16_as_ushort(h2) | ((uint32_t)__bfloat16_as_ushort(h3) << 16));
            uint2 lp = make_uint2((uint32_t)__bfloat16_as_ushort(l0) | ((uint32_t)__bfloat16_as_ushort(l1) << 16),
                                  (uint32_t)__bfloat16_as_ushort(l2) | ((uint32_t)__bfloat16_as_ushort(l3) << 16));
            const uint32_t off = (uint32_t)(col >> 5) * 16384u
                               + swz(arow, (col & 31) >> 3) + ((col & 4) ? 8u : 0u);
            *(uint2*)(smem + off) = hp;
            *(uint2*)(smem + off + 8192u) = lp;
        }
    }

#pragma unroll
    for (int i = 0; i < 4; ++i)
#pragma unroll
        for (int j = 0; j < 4; ++j)
#pragma unroll
            for (int q = 0; q < 4; ++q) acc[i][j][q] = 0.f;

    for (int c = 0; c < 4; ++c) {
        if (c < 3) { CP_WAIT(1); } else { CP_WAIT(0); }
        __syncthreads();
        if (c + 2 < 4) issueB(W1h, W1l, 128, c + 2, 4, 32768);
        const uint32_t st = STG + (uint32_t)(c % 3) * 32768u;
        chunk_mma<4>(ACT + (uint32_t)c * 16384u, st + (uint32_t)nb * 16384u,
                     mo, no_l, lid, acc);
    }
    __syncthreads();
    issueB(W2h, W2l, 256, 0, 4, 32768);
    issueB(W2h, W2l, 256, 1, 4, 32768);
    epi_to_act<4>(acc, b1, ACT, mo, no_g, lid);

    // ================= layer 2: K=256 (8 chunks) =================
#pragma unroll
    for (int i = 0; i < 4; ++i)
#pragma unroll
        for (int j = 0; j < 4; ++j)
#pragma unroll
            for (int q = 0; q < 4; ++q) acc[i][j][q] = 0.f;

    for (int c = 0; c < 8; ++c) {
        if (c < 7) { CP_WAIT(1); } else { CP_WAIT(0); }
        __syncthreads();
        if (c + 2 < 8) issueB(W2h, W2l, 256, c + 2, 4, 32768);
        const uint32_t st = STG + (uint32_t)(c % 3) * 32768u;
        chunk_mma<4>(ACT + (uint32_t)c * 16384u, st + (uint32_t)nb * 16384u,
                     mo, no_l, lid, acc);
    }
    __syncthreads();
    issueB(W3h, W3l, 256, 0, 2, 16384);
    issueB(W3h, W3l, 256, 1, 2, 16384);
    epi_to_act<4>(acc, b2, ACT, mo, no_g, lid);

    // ================= layer 3: K=256 (8 chunks), M=128, 16KB stages =============
    float (&acc3)[2][4][4] = *reinterpret_cast<float(*)[2][4][4]>(acc);
#pragma unroll
    for (int i = 0; i < 2; ++i)
#pragma unroll
        for (int j = 0; j < 4; ++j)
#pragma unroll
            for (int q = 0; q < 4; ++q) acc3[i][j][q] = 0.f;

    for (int c = 0; c < 8; ++c) {
        if (c < 7) { CP_WAIT(1); } else { CP_WAIT(0); }
        __syncthreads();
        if (c + 2 < 8) issueB(W3h, W3l, 256, c + 2, 2, 16384);
        chunk_mma<2>(ACT + (uint32_t)c * 16384u, STG + (uint32_t)(c % 3) * 16384u,
                     mo3, no3, lid, acc3);
    }

    // ---- final epilogue: bias + leaky-relu (+ optional masked residual) ----
    {
        const int g = lid >> 2;
        const int t2c = (lid & 3) << 1;
#pragma unroll
        for (int i = 0; i < 2; ++i) {
            const int row0 = bm + mo3 + i * 16 + g;
#pragma unroll
            for (int j = 0; j < 4; ++j) {
                const int col = no3 + j * 8 + t2c;
                const float2 bv = *(const float2*)(b3 + col);
#pragma unroll
                for (int h = 0; h < 2; ++h) {
                    const int row = row0 + h * 8;
                    if (row >= Nrows) continue;
                    float2 o;
                    o.x = acc3[i][j][h * 2 + 0] + bv.x;
                    o.y = acc3[i][j][h * 2 + 1] + bv.y;
                    o.x = o.x >= 0.f ? o.x : 0.01f * o.x;
                    o.y = o.y >= 0.f ? o.y : 0.01f * o.y;
                    const size_t off = (size_t)row * 128 + col;
                    if (xin) {
                        const float m = maskp[row];
                        const float2 xv = *(const float2*)(xin + off);
                        o.x = xv.x + m * o.x;
                        o.y = xv.y + m * o.y;
                    }
                    *(float2*)(Cf + off) = o;
                }
            }
        }
    }
}

// ---------------- weight prep: all 6 matrices, one launch ----------------
__global__ void prep_all(const float* __restrict__ h1, const float* __restrict__ h2,
                         const float* __restrict__ h3, const float* __restrict__ f1,
                         const float* __restrict__ f2, const float* __restrict__ f3,
                         __nv_bfloat16* __restrict__ hi, __nv_bfloat16* __restrict__ lo)
{
    int idx = blockIdx.x * blockDim.x + threadIdx.x;
    if (idx >= 262144) return;
    const float* W; int K, M, off, li;
    if      (idx <  32768) { W = h1; K = 128; M = 256; off = 0;      li = idx; }
    else if (idx <  98304) { W = h2; K = 256; M = 256; off = 32768;  li = idx - 32768; }
    else if (idx < 131072) { W = h3; K = 256; M = 128; off = 98304;  li = idx - 98304; }
    else if (idx < 163840) { W = f1; K = 128; M = 256; off = 131072; li = idx - 131072; }
    else if (idx < 229376) { W = f2; K = 256; M = 256; off = 163840; li = idx - 163840; }
    else                   { W = f3; K = 256; M = 128; off = 229376; li = idx - 229376; }
    int k = li / M, m = li - k * M;
    float v = W[li];
    __nv_bfloat16 h, l;
    split1(v, h, l);
    hi[off + (size_t)m * K + k] = h;
    lo[off + (size_t)m * K + k] = l;
}

// ---------------- CSR build ----------------
__global__ void zero_int(int* __restrict__ p, int n)
{
    int i = blockIdx.x * blockDim.x + threadIdx.x;
    if (i < n) p[i] = 0;
}

__global__ void hist_kernel(const int* __restrict__ src, int* __restrict__ cnt)
{
    int idx = blockIdx.x * blockDim.x + threadIdx.x;
    if (idx >= DEPTH * EE / 4) return;
    int4 s4 = ((const int4*)src)[idx];
    int d = (idx << 2) / EE;
    int* c = cnt + d * NN;
    atomicAdd(&c[s4.x], 1);
    atomicAdd(&c[s4.y], 1);
    atomicAdd(&c[s4.z], 1);
    atomicAdd(&c[s4.w], 1);
}

// one CTA per depth; warp-shuffle scan; writes rp AND cur
__global__ void scan_kernel(const int* __restrict__ cnt, int* __restrict__ rp,
                            int* __restrict__ cur)
{
    const int d = blockIdx.x;
    const int t = threadIdx.x;           // 1024
    const int CH = 49;
    __shared__ int wtot[32];
    const int base = t * CH;
    int sum = 0;
    for (int i = 0; i < CH; ++i) {
        int idx = base + i;
        if (idx < NN) sum += cnt[d * NN + idx];
    }
    const int lane = t & 31, warp = t >> 5;
    int v = sum;
#pragma unroll
    for (int o = 1; o < 32; o <<= 1) {
        int u = __shfl_up_sync(0xFFFFFFFFu, v, o);
        if (lane >= o) v += u;
    }
    if (lane == 31) wtot[warp] = v;
    __syncthreads();
    if (warp == 0) {
        int w = wtot[lane];
#pragma unroll
        for (int o = 1; o < 32; o <<= 1) {
            int u = __shfl_up_sync(0xFFFFFFFFu, w, o);
            if (lane >= o) w += u;
        }
        wtot[lane] = w;
    }
    __syncthreads();
    int run = (v - sum) + (warp ? wtot[warp - 1] : 0);
    for (int i = 0; i < CH; ++i) {
        int idx = base + i;
        if (idx < NN) {
            rp[d * (NN + 1) + idx] = run;
            cur[d * NN + idx] = run;
            run += cnt[d * NN + idx];
        }
    }
    if (t == 1023) rp[d * (NN + 1) + NN] = run;
}

__global__ void fill_kernel(const int* __restrict__ src, const int* __restrict__ dst,
                            const float* __restrict__ vals, int* __restrict__ cur,
                            int* __restrict__ col, float* __restrict__ val)
{
    int idx = blockIdx.x * blockDim.x + threadIdx.x;
    if (idx >= DEPTH * EE / 4) return;
    int4 s4 = ((const int4*)src)[idx];
    int4 t4 = ((const int4*)dst)[idx];
    float4 v4 = ((const float4*)vals)[idx];
    int d = (idx << 2) / EE;
    int* cu = cur + d * NN;
    int* co = col + (size_t)d * EE;
    float* va = val + (size_t)d * EE;
    int p;
    p = atomicAdd(&cu[s4.x], 1); co[p] = t4.x; va[p] = v4.x;
    p = atomicAdd(&cu[s4.y], 1); co[p] = t4.y; va[p] = v4.y;
    p = atomicAdd(&cu[s4.z], 1); co[p] = t4.z; va[p] = v4.z;
    p = atomicAdd(&cu[s4.w], 1); co[p] = t4.w; va[p] = v4.w;
}

// ---------------- gather: s[n] = sum_{e in CSR[n]} val_e * y[col_e] --------------
__global__ void gather_kernel(const int* __restrict__ rp, const int* __restrict__ col,
                              const float* __restrict__ val,
                              const float* __restrict__ y, float* __restrict__ out)
{
    int gid = blockIdx.x * blockDim.x + threadIdx.x;
    int node = gid >> 5;
    int lane = gid & 31;
    if (node >= NN) return;
    int beg = rp[node], end = rp[node + 1];
    float4 acc = make_float4(0.f, 0.f, 0.f, 0.f);
    for (int i = beg; i < end; ++i) {
        int dn = col[i];
        float v = val[i];
        float4 yv = ((const float4*)y)[(size_t)dn * 32 + lane];
        acc.x += v * yv.x; acc.y += v * yv.y;
        acc.z += v * yv.z; acc.w += v * yv.w;
    }
    ((float4*)out)[(size_t)node * 32 + lane] = acc;
}

// ---------------- host orchestration ----------------
static const int FUSED_SMEM = 131072 + 98304;   // act 128KB + stages 96KB = 224KB

extern "C" void kernel_launch(void* const* d_in, const int* in_sizes, int n_in,
                              void* d_out, int out_size)
{
    const float* node_inputs = (const float*)d_in[0];
    const int*   edge_src    = (const int*)  d_in[1];
    const int*   edge_dst    = (const int*)  d_in[2];
    const float* adj_vals    = (const float*)d_in[3];
    const float* masks       = (const float*)d_in[4];
    const float* W_h1 = (const float*)d_in[5];
    const float* b_h1 = (const float*)d_in[6];
    const float* W_h2 = (const float*)d_in[7];
    const float* b_h2 = (const float*)d_in[8];
    const float* W_h3 = (const float*)d_in[9];
    const float* b_h3 = (const float*)d_in[10];
    const float* W_f1 = (const float*)d_in[11];
    const float* b_f1 = (const float*)d_in[12];
    const float* W_f2 = (const float*)d_in[13];
    const float* b_f2 = (const float*)d_in[14];
    const float* W_f3 = (const float*)d_in[15];
    const float* b_f3 = (const float*)d_in[16];

    float* x = (float*)d_out;

    float *y, *s, *valp;
    __nv_bfloat16 *whi, *wlo;
    int *cnt, *cur, *rp, *colp;
    cudaGetSymbolAddress((void**)&y,    g_y);
    cudaGetSymbolAddress((void**)&s,    g_s);
    cudaGetSymbolAddress((void**)&whi,  g_wt_hi);
    cudaGetSymbolAddress((void**)&wlo,  g_wt_lo);
    cudaGetSymbolAddress((void**)&cnt,  g_cnt);
    cudaGetSymbolAddress((void**)&cur,  g_cur);
    cudaGetSymbolAddress((void**)&rp,   g_rp);
    cudaGetSymbolAddress((void**)&colp, g_col);
    cudaGetSymbolAddress((void**)&valp, g_val);

    cudaFuncSetAttribute(fused_mlp3, cudaFuncAttributeMaxDynamicSharedMemorySize, FUSED_SMEM);

    const int OH1 = 0, OH2 = 32768, OH3 = 98304, OF1 = 131072, OF2 = 163840, OF3 = 229376;

    // weight prep + CSR build (once per call)
    prep_all<<<262144 / 256, 256>>>(W_h1, W_h2, W_h3, W_f1, W_f2, W_f3, whi, wlo);
    zero_int<<<(DEPTH * NN + 255) / 256, 256>>>(cnt, DEPTH * NN);
    hist_kernel<<<(DEPTH * EE / 4 + 255) / 256, 256>>>(edge_src, cnt);
    scan_kernel<<<DEPTH, 1024>>>(cnt, rp, cur);
    fill_kernel<<<(DEPTH * EE / 4 + 255) / 256, 256>>>(edge_src, edge_dst, adj_vals,
                                                       cur, colp, valp);

    const int GRID = (NN + 127) / 128;   // 391
    const int GATHER_BLOCKS = (NN * 32 + 255) / 256;

    // embedding MLP: x = mlp3(node_inputs; W_h*)
    fused_mlp3<<<GRID, NTHREADS, FUSED_SMEM>>>(node_inputs,
        whi + OH1, wlo + OH1, whi + OH2, wlo + OH2, whi + OH3, wlo + OH3,
        b_h1, b_h2, b_h3, x, nullptr, nullptr, NN);

    for (int d = 0; d < DEPTH; d++) {
        // y = mlp3(x)
        fused_mlp3<<<GRID, NTHREADS, FUSED_SMEM>>>(x,
            whi + OF1, wlo + OF1, whi + OF2, wlo + OF2, whi + OF3, wlo + OF3,
            b_f1, b_f2, b_f3, y, nullptr, nullptr, NN);

        // s = segment_sum(adj_vals * y[dst], src)  — CSR gather, no atomics
        gather_kernel<<<GATHER_BLOCKS, 256>>>(rp + d * (NN + 1),
                                              colp + (size_t)d * EE,
                                              valp + (size_t)d * EE, y, s);

        // x = x + mask[d] * mlp3(s)   (residual fused into epilogue)
        fused_mlp3<<<GRID, NTHREADS, FUSED_SMEM>>>(s,
            whi + OF1, wlo + OF1, whi + OF2, wlo + OF2, whi + OF3, wlo + OF3,
            b_f1, b_f2, b_f3, x, x, masks + (size_t)d * NN, NN);
    }
}

// round 9
// speedup vs baseline: 2.8635x; 1.0034x over previous
#include <cuda_runtime.h>
#include <cuda_bf16.h>
#include <cstdint>

#define NN 50000
#define EE 600000
#define DEPTH 8
#define NTHREADS 512
#define NBLK 98            // ceil(NN / 512)

// ---------------- scratch (alloc-free rule: __device__ globals) ----------------
__device__ __align__(16) float g_y[NN * 128];
__device__ __align__(16) __nv_bfloat16 g_wt_hi[262144];
__device__ __align__(16) __nv_bfloat16 g_wt_lo[262144];
// CSR per depth
__device__ int  g_cnt[DEPTH * NN];
__device__ int  g_cur[DEPTH * NN];
__device__ int  g_rp [DEPTH * (NN + 1)];
__device__ int  g_part[DEPTH * NBLK];
__device__ __align__(16) int2 g_cv[DEPTH * EE];   // {dst, val bits}

// ---------------- helpers ----------------
__device__ __forceinline__ uint32_t smem_to_u32(const void* smem_ptr) {
    uint32_t addr;
    asm("{ .reg .u64 tmp; cvta.to.shared.u64 tmp, %1; cvt.u32.u64 %0, tmp; }"
        : "=r"(addr) : "l"(smem_ptr));
    return addr;
}

__device__ __forceinline__ void ldmx4(uint32_t* d, uint32_t addr) {
    asm volatile("ldmatrix.sync.aligned.m8n8.x4.shared.b16 {%0,%1,%2,%3}, [%4];"
                 : "=r"(d[0]), "=r"(d[1]), "=r"(d[2]), "=r"(d[3]) : "r"(addr));
}

__device__ __forceinline__ void mma16816(float* c, const uint32_t* a, const uint32_t* b) {
    asm volatile(
        "mma.sync.aligned.m16n8k16.row.col.f32.bf16.bf16.f32 "
        "{%0,%1,%2,%3},{%4,%5,%6,%7},{%8,%9},{%0,%1,%2,%3};"
        : "+f"(c[0]), "+f"(c[1]), "+f"(c[2]), "+f"(c[3])
        : "r"(a[0]), "r"(a[1]), "r"(a[2]), "r"(a[3]), "r"(b[0]), "r"(b[1]));
}

__device__ __forceinline__ void cp16(uint32_t smem_addr, const void* gptr, int srcbytes) {
    asm volatile("cp.async.cg.shared.global [%0], [%1], 16, %2;"
                 :: "r"(smem_addr), "l"(gptr), "r"(srcbytes) : "memory");
}
#define CP_COMMIT() asm volatile("cp.async.commit_group;" ::: "memory")
#define CP_WAIT(n)  asm volatile("cp.async.wait_group %0;" :: "n"(n) : "memory")

// swizzled byte offset within a 128x32 bf16 tile (row stride 64B, 16B groups XORed)
__device__ __forceinline__ uint32_t swz(int row, int c16) {
    return (uint32_t)(row * 64) + (uint32_t)(((c16 ^ ((row >> 1) & 3)) << 4));
}

__device__ __forceinline__ void split1(float v, __nv_bfloat16& h, __nv_bfloat16& l) {
    h = __float2bfloat16(v);
    l = __float2bfloat16(v - __bfloat162float(h));
}

// ---- one K=32 chunk of split-bf16 MMA for one warp tile (MI m16-tiles x 32 cols).
template<int MI>
__device__ __forceinline__ void chunk_mma(uint32_t Abase, uint32_t Bbase,
                                          int mo, int no, int lid,
                                          float acc[MI][4][4])
{
    const int lrow = lid & 15;
    const int lc = lid >> 4;
#pragma unroll
    for (int ks = 0; ks < 2; ++ks) {
        const int cA = (ks << 1) + lc;
        uint32_t bfh[4][2], bfl[4][2];
#pragma unroll
        for (int jj = 0; jj < 2; ++jj) {
            const int row = no + jj * 16 + lrow;
            const uint32_t so = swz(row, cA);
            uint32_t r4[4];
            ldmx4(r4, Bbase + so);
            bfh[jj * 2 + 0][0] = r4[0]; bfh[jj * 2 + 0][1] = r4[2];
            bfh[jj * 2 + 1][0] = r4[1]; bfh[jj * 2 + 1][1] = r4[3];
            ldmx4(r4, Bbase + 8192u + so);
            bfl[jj * 2 + 0][0] = r4[0]; bfl[jj * 2 + 0][1] = r4[2];
            bfl[jj * 2 + 1][0] = r4[1]; bfl[jj * 2 + 1][1] = r4[3];
        }
#pragma unroll
        for (int i = 0; i < MI; ++i) {
            const int row = mo + i * 16 + lrow;
            const uint32_t so = swz(row, cA);
            uint32_t afh[4], afl[4];
            ldmx4(afh, Abase + so);
            ldmx4(afl, Abase + 8192u + so);
#pragma unroll
            for (int j = 0; j < 4; ++j) {
                mma16816(acc[i][j], afh, bfh[j]);
                mma16816(acc[i][j], afh, bfl[j]);
                mma16816(acc[i][j], afl, bfh[j]);
            }
        }
    }
}

// ---- epilogue into act smem: bias + leaky-relu + bf16 split ----
template<int MI>
__device__ __forceinline__ void epi_to_act(float acc[MI][4][4], const float* bias,
                                           uint32_t act, int mo, int no_g, int lid)
{
    const int g = lid >> 2;
    const int t2c = (lid & 3) << 1;
#pragma unroll
    for (int i = 0; i < MI; ++i) {
        const int row0 = mo + i * 16 + g;
#pragma unroll
        for (int j = 0; j < 4; ++j) {
            const int col = no_g + j * 8 + t2c;
            const float2 bv = *(const float2*)(bias + col);
            const uint32_t cbase = act + (uint32_t)(col >> 5) * 16384u;
            const int c16 = (col & 31) >> 3;
            const uint32_t sub = (uint32_t)((col & 7) << 1);
#pragma unroll
            for (int h = 0; h < 2; ++h) {
                const int row = row0 + h * 8;
                float ox = acc[i][j][h * 2 + 0] + bv.x;
                float oy = acc[i][j][h * 2 + 1] + bv.y;
                ox = ox >= 0.f ? ox : 0.01f * ox;
                oy = oy >= 0.f ? oy : 0.01f * oy;
                __nv_bfloat16 hx, lx, hy, ly;
                split1(ox, hx, lx);
                split1(oy, hy, ly);
                uint32_t hp = (uint32_t)__bfloat16_as_ushort(hx) | ((uint32_t)__bfloat16_as_ushort(hy) << 16);
                uint32_t lp = (uint32_t)__bfloat16_as_ushort(lx) | ((uint32_t)__bfloat16_as_ushort(ly) << 16);
                const uint32_t ad = cbase + swz(row, c16) + sub;
                asm volatile("st.shared.b32 [%0], %1;" :: "r"(ad), "r"(hp) : "memory");
                asm volatile("st.shared.b32 [%0], %1;" :: "r"(ad + 8192u), "r"(lp) : "memory");
            }
        }
    }
}

// ---------------- fused MLP3 (fp32 in / fp32 out, optional residual+CSR gather) --
// If cvg != null: A rows are gathered from y via CSR (segment_sum) instead of Ag.
// out = lrelu(mlp3(A)); if xin: Cf = xin + mask*out  else Cf = out
__global__ __launch_bounds__(NTHREADS, 1)
void fused_mlp3(const float* __restrict__ Ag,
                const __nv_bfloat16* __restrict__ W1h, const __nv_bfloat16* __restrict__ W1l,
                const __nv_bfloat16* __restrict__ W2h, const __nv_bfloat16* __restrict__ W2l,
                const __nv_bfloat16* __restrict__ W3h, const __nv_bfloat16* __restrict__ W3l,
                const float* __restrict__ b1, const float* __restrict__ b2,
                const float* __restrict__ b3,
                const int* __restrict__ rpg, const int2* __restrict__ cvg,
                const float* __restrict__ yg,
                float* __restrict__ Cf, const float* __restrict__ xin,
                const float* __restrict__ maskp, int Nrows)
{
    extern __shared__ char smem[];
    const uint32_t sb = smem_to_u32(smem);
    const uint32_t ACT = sb;                 // 128KB: chunk c at +c*16384 {hi, +8192 lo}
    const uint32_t STG = sb + 131072u;       // 96KB stage region

    const int tid = threadIdx.x;
    const int wid = tid >> 5;
    const int lid = tid & 31;
    const int bm = blockIdx.x * 128;
    // layer 1/2 warp tile (64x32): 2 m-groups x 8 n-groups
    const int mo = (wid >> 3) * 64;
    const int no_g = (wid & 7) * 32;
    const int nb = no_g >> 7;
    const int no_l = no_g & 127;
    // layer 3 warp tile (32x32): 4 x 4
    const int mo3 = (wid >> 2) * 32;
    const int no3 = (wid & 3) * 32;

    auto issueB = [&](const __nv_bfloat16* Wh, const __nv_bfloat16* Wl,
                      int kstride, int c, int iters, int stgsz) {
        const int k0 = c << 5;
        const uint32_t st = STG + (uint32_t)(c % 3) * (uint32_t)stgsz;
        for (int it = 0; it < iters; ++it) {
            const int q = it * NTHREADS + tid;
            const int reg = q >> 9;
            const int w = q & 511;
            const int row = w >> 2;
            const int c16 = w & 3;
            const int blk = reg >> 1;
            const __nv_bfloat16* base = (reg & 1) ? Wl : Wh;
            const __nv_bfloat16* src = base + (size_t)(blk * 128 + row) * kstride + k0 + (c16 << 3);
            cp16(st + (uint32_t)reg * 8192u + swz(row, c16), src, 16);
        }
        CP_COMMIT();
    };

    float acc[4][4][4];

    // ================= layer 1: K=128 (4 chunks), 32KB stages =================
    issueB(W1h, W1l, 128, 0, 4, 32768);
    issueB(W1h, W1l, 128, 1, 4, 32768);

    // ---- A into ACT slots 0..3: either plain rows (split) or CSR gather ----
    if (cvg) {
        // CSR gather: warp w handles local rows w*8..w*8+7; lane covers 4 cols
#pragma unroll 1
        for (int q8 = 0; q8 < 8; ++q8) {
            const int r = (wid << 3) + q8;
            const int nd = bm + r;
            float4 a4 = make_float4(0.f, 0.f, 0.f, 0.f);
            if (nd < Nrows) {
                const int beg = rpg[nd], end = rpg[nd + 1];
                for (int i = beg; i < end; ++i) {
                    const int2 e = cvg[i];
                    const float v = __int_as_float(e.y);
                    const float4 yv = ((const float4*)yg)[(size_t)e.x * 32 + lid];
                    a4.x += v * yv.x; a4.y += v * yv.y;
                    a4.z += v * yv.z; a4.w += v * yv.w;
                }
            }
            __nv_bfloat16 h0, l0, h1, l1, h2, l2, h3, l3;
            split1(a4.x, h0, l0); split1(a4.y, h1, l1);
            split1(a4.z, h2, l2); split1(a4.w, h3, l3);
            uint2 hp = make_uint2((uint32_t)__bfloat16_as_ushort(h0) | ((uint32_t)__bfloat16_as_ushort(h1) << 16),
                                  (uint32_t)__bfloat16_as_ushort(h2) | ((uint32_t)__bfloat16_as_ushort(h3) << 16));
            uint2 lp = make_uint2((uint32_t)__bfloat16_as_ushort(l0) | ((uint32_t)__bfloat16_as_ushort(l1) << 16),
                                  (uint32_t)__bfloat16_as_ushort(l2) | ((uint32_t)__bfloat16_as_ushort(l3) << 16));
            const int col = lid << 2;
            const uint32_t off = (uint32_t)(col >> 5) * 16384u
                               + swz(r, (col & 31) >> 3) + ((col & 4) ? 8u : 0u);
            *(uint2*)(smem + off) = hp;
            *(uint2*)(smem + off + 8192u) = lp;
        }
    } else {
        const int arow = tid >> 2;
        const int acol0 = (tid & 3) << 5;
        const int grow = bm + arow;
        const float* arp = Ag + (size_t)grow * 128 + acol0;
#pragma unroll
        for (int i = 0; i < 8; ++i) {
            const int col = acol0 + i * 4;
            float4 v = (grow < Nrows) ? *(const float4*)(arp + i * 4)
                                      : make_float4(0.f, 0.f, 0.f, 0.f);
            __nv_bfloat16 h0, l0, h1, l1, h2, l2, h3, l3;
            split1(v.x, h0, l0); split1(v.y, h1, l1);
            split1(v.z, h2, l2); split1(v.w, h3, l3);
            uint2 hp = make_uint2((uint32_t)__bfloat16_as_ushort(h0) | ((uint32_t)__bfloat16_as_ushort(h1) << 16),
                                  (uint32_t)__bfloat16_as_ushort(h2) | ((uint32_t)__bfloat16_as_ushort(h3) << 16));
            uint2 lp = make_uint2((uint32_t)__bfloat16_as_ushort(l0) | ((uint32_t)__bfloat16_as_ushort(l1) << 16),
                                  (uint32_t)__bfloat16_as_ushort(l2) | ((uint32_t)__bfloat16_as_ushort(l3) << 16));
            const uint32_t off = (uint32_t)(col >> 5) * 16384u
                               + swz(arow, (col & 31) >> 3) + ((col & 4) ? 8u : 0u);
            *(uint2*)(smem + off) = hp;
            *(uint2*)(smem + off + 8192u) = lp;
        }
    }

#pragma unroll
    for (int i = 0; i < 4; ++i)
#pragma unroll
        for (int j = 0; j < 4; ++j)
#pragma unroll
            for (int q = 0; q < 4; ++q) acc[i][j][q] = 0.f;

    for (int c = 0; c < 4; ++c) {
        if (c < 3) { CP_WAIT(1); } else { CP_WAIT(0); }
        __syncthreads();
        if (c + 2 < 4) issueB(W1h, W1l, 128, c + 2, 4, 32768);
        const uint32_t st = STG + (uint32_t)(c % 3) * 32768u;
        chunk_mma<4>(ACT + (uint32_t)c * 16384u, st + (uint32_t)nb * 16384u,
                     mo, no_l, lid, acc);
    }
    __syncthreads();
    issueB(W2h, W2l, 256, 0, 4, 32768);
    issueB(W2h, W2l, 256, 1, 4, 32768);
    epi_to_act<4>(acc, b1, ACT, mo, no_g, lid);

    // ================= layer 2: K=256 (8 chunks) =================
#pragma unroll
    for (int i = 0; i < 4; ++i)
#pragma unroll
        for (int j = 0; j < 4; ++j)
#pragma unroll
            for (int q = 0; q < 4; ++q) acc[i][j][q] = 0.f;

    for (int c = 0; c < 8; ++c) {
        if (c < 7) { CP_WAIT(1); } else { CP_WAIT(0); }
        __syncthreads();
        if (c + 2 < 8) issueB(W2h, W2l, 256, c + 2, 4, 32768);
        const uint32_t st = STG + (uint32_t)(c % 3) * 32768u;
        chunk_mma<4>(ACT + (uint32_t)c * 16384u, st + (uint32_t)nb * 16384u,
                     mo, no_l, lid, acc);
    }
    __syncthreads();
    issueB(W3h, W3l, 256, 0, 2, 16384);
    issueB(W3h, W3l, 256, 1, 2, 16384);
    epi_to_act<4>(acc, b2, ACT, mo, no_g, lid);

    // ================= layer 3: K=256 (8 chunks), M=128, 16KB stages =============
    float (&acc3)[2][4][4] = *reinterpret_cast<float(*)[2][4][4]>(acc);
#pragma unroll
    for (int i = 0; i < 2; ++i)
#pragma unroll
        for (int j = 0; j < 4; ++j)
#pragma unroll
            for (int q = 0; q < 4; ++q) acc3[i][j][q] = 0.f;

    for (int c = 0; c < 8; ++c) {
        if (c < 7) { CP_WAIT(1); } else { CP_WAIT(0); }
        __syncthreads();
        if (c + 2 < 8) issueB(W3h, W3l, 256, c + 2, 2, 16384);
        chunk_mma<2>(ACT + (uint32_t)c * 16384u, STG + (uint32_t)(c % 3) * 16384u,
                     mo3, no3, lid, acc3);
    }

    // ---- final epilogue: bias + leaky-relu (+ optional masked residual) ----
    {
        const int g = lid >> 2;
        const int t2c = (lid & 3) << 1;
#pragma unroll
        for (int i = 0; i < 2; ++i) {
            const int row0 = bm + mo3 + i * 16 + g;
#pragma unroll
            for (int j = 0; j < 4; ++j) {
                const int col = no3 + j * 8 + t2c;
                const float2 bv = *(const float2*)(b3 + col);
#pragma unroll
                for (int h = 0; h < 2; ++h) {
                    const int row = row0 + h * 8;
                    if (row >= Nrows) continue;
                    float2 o;
                    o.x = acc3[i][j][h * 2 + 0] + bv.x;
                    o.y = acc3[i][j][h * 2 + 1] + bv.y;
                    o.x = o.x >= 0.f ? o.x : 0.01f * o.x;
                    o.y = o.y >= 0.f ? o.y : 0.01f * o.y;
                    const size_t off = (size_t)row * 128 + col;
                    if (xin) {
                        const float m = maskp[row];
                        const float2 xv = *(const float2*)(xin + off);
                        o.x = xv.x + m * o.x;
                        o.y = xv.y + m * o.y;
                    }
                    *(float2*)(Cf + off) = o;
                }
            }
        }
    }
}

// ---------------- weight prep: all 6 matrices, one launch ----------------
__global__ void prep_all(const float* __restrict__ h1, const float* __restrict__ h2,
                         const float* __restrict__ h3, const float* __restrict__ f1,
                         const float* __restrict__ f2, const float* __restrict__ f3,
                         __nv_bfloat16* __restrict__ hi, __nv_bfloat16* __restrict__ lo)
{
    int idx = blockIdx.x * blockDim.x + threadIdx.x;
    if (idx >= 262144) return;
    const float* W; int K, M, off, li;
    if      (idx <  32768) { W = h1; K = 128; M = 256; off = 0;      li = idx; }
    else if (idx <  98304) { W = h2; K = 256; M = 256; off = 32768;  li = idx - 32768; }
    else if (idx < 131072) { W = h3; K = 256; M = 128; off = 98304;  li = idx - 98304; }
    else if (idx < 163840) { W = f1; K = 128; M = 256; off = 131072; li = idx - 131072; }
    else if (idx < 229376) { W = f2; K = 256; M = 256; off = 163840; li = idx - 163840; }
    else                   { W = f3; K = 256; M = 128; off = 229376; li = idx - 229376; }
    int k = li / M, m = li - k * M;
    float v = W[li];
    __nv_bfloat16 h, l;
    split1(v, h, l);
    hi[off + (size_t)m * K + k] = h;
    lo[off + (size_t)m * K + k] = l;
}

// ---------------- CSR build ----------------
__global__ void zero_int(int* __restrict__ p, int n)
{
    int i = blockIdx.x * blockDim.x + threadIdx.x;
    if (i < n) p[i] = 0;
}

__global__ void hist_kernel(const int* __restrict__ src, int* __restrict__ cnt)
{
    int idx = blockIdx.x * blockDim.x + threadIdx.x;
    if (idx >= DEPTH * EE / 4) return;
    int4 s4 = ((const int4*)src)[idx];
    int d = (idx << 2) / EE;
    int* c = cnt + d * NN;
    atomicAdd(&c[s4.x], 1);
    atomicAdd(&c[s4.y], 1);
    atomicAdd(&c[s4.z], 1);
    atomicAdd(&c[s4.w], 1);
}

// phase A: per-block sums (grid DEPTH*NBLK, 512 threads)
__global__ void part_kernel(const int* __restrict__ cnt, int* __restrict__ part)
{
    const int blk = blockIdx.x;
    const int d = blk / NBLK, b = blk - d * NBLK;
    const int t = threadIdx.x;
    const int idx = b * 512 + t;
    int c = (idx < NN) ? cnt[d * NN + idx] : 0;
#pragma unroll
    for (int o = 16; o > 0; o >>= 1) c += __shfl_down_sync(0xFFFFFFFFu, c, o);
    __shared__ int wsum[16];
    if ((t & 31) == 0) wsum[t >> 5] = c;
    __syncthreads();
    if (t < 16) {
        int v = wsum[t];
#pragma unroll
        for (int o = 8; o > 0; o >>= 1) v += __shfl_down_sync(0xFFFFu, v, o);
        if (t == 0) part[blk] = v;
    }
}

// phase B: exclusive scan of NBLK partials per depth (grid DEPTH, 128 threads)
__global__ void scanp_kernel(int* __restrict__ part)
{
    __shared__ int sm[128];
    const int d = blockIdx.x, t = threadIdx.x;
    int v = (t < NBLK) ? part[d * NBLK + t] : 0;
    sm[t] = v;
    __syncthreads();
    for (int o = 1; o < 128; o <<= 1) {
        int u = (t >= o) ? sm[t - o] : 0;
        __syncthreads();
        sm[t] += u;
        __syncthreads();
    }
    if (t < NBLK) part[d * NBLK + t] = sm[t] - v;
}

// phase C: local scan + offset -> rp, cur (grid DEPTH*NBLK, 512 threads)
__global__ void scan2_kernel(const int* __restrict__ cnt, const int* __restrict__ part,
                             int* __restrict__ rp, int* __restrict__ cur)
{
    const int blk = blockIdx.x;
    const int d = blk / NBLK, b = blk - d * NBLK;
    const int t = threadIdx.x;
    const int idx = b * 512 + t;
    const int lane = t & 31, warp = t >> 5;
    int c = (idx < NN) ? cnt[d * NN + idx] : 0;
    int v = c;
#pragma unroll
    for (int o = 1; o < 32; o <<= 1) {
        int u = __shfl_up_sync(0xFFFFFFFFu, v, o);
        if (lane >= o) v += u;
    }
    __shared__ int wt[16];
    if (lane == 31) wt[warp] = v;
    __syncthreads();
    if (warp == 0 && lane < 16) {
        int w = wt[lane];
#pragma unroll
        for (int o = 1; o < 16; o <<= 1) {
            int u = __shfl_up_sync(0xFFFFu, w, o);
            if (lane >= o) w += u;
        }
        wt[lane] = w;
    }
    __syncthreads();
    const int excl = (v - c) + (warp ? wt[warp - 1] : 0) + part[blk];
    if (idx < NN) {
        rp[d * (NN + 1) + idx] = excl;
        cur[d * NN + idx] = excl;
    }
    if (b == 0 && t == 0) rp[d * (NN + 1) + NN] = EE;   // total per depth is constant
}

__global__ void fill_kernel(const int* __restrict__ src, const int* __restrict__ dst,
                            const float* __restrict__ vals, int* __restrict__ cur,
                            int2* __restrict__ cv)
{
    int idx = blockIdx.x * blockDim.x + threadIdx.x;
    if (idx >= DEPTH * EE / 4) return;
    int4 s4 = ((const int4*)src)[idx];
    int4 t4 = ((const int4*)dst)[idx];
    float4 v4 = ((const float4*)vals)[idx];
    int d = (idx << 2) / EE;
    int* cu = cur + d * NN;
    int2* cvd = cv + (size_t)d * EE;
    int p;
    p = atomicAdd(&cu[s4.x], 1); cvd[p] = make_int2(t4.x, __float_as_int(v4.x));
    p = atomicAdd(&cu[s4.y], 1); cvd[p] = make_int2(t4.y, __float_as_int(v4.y));
    p = atomicAdd(&cu[s4.z], 1); cvd[p] = make_int2(t4.z, __float_as_int(v4.z));
    p = atomicAdd(&cu[s4.w], 1); cvd[p] = make_int2(t4.w, __float_as_int(v4.w));
}

// ---------------- host orchestration ----------------
static const int FUSED_SMEM = 131072 + 98304;   // act 128KB + stages 96KB = 224KB

extern "C" void kernel_launch(void* const* d_in, const int* in_sizes, int n_in,
                              void* d_out, int out_size)
{
    const float* node_inputs = (const float*)d_in[0];
    const int*   edge_src    = (const int*)  d_in[1];
    const int*   edge_dst    = (const int*)  d_in[2];
    const float* adj_vals    = (const float*)d_in[3];
    const float* masks       = (const float*)d_in[4];
    const float* W_h1 = (const float*)d_in[5];
    const float* b_h1 = (const float*)d_in[6];
    const float* W_h2 = (const float*)d_in[7];
    const float* b_h2 = (const float*)d_in[8];
    const float* W_h3 = (const float*)d_in[9];
    const float* b_h3 = (const float*)d_in[10];
    const float* W_f1 = (const float*)d_in[11];
    const float* b_f1 = (const float*)d_in[12];
    const float* W_f2 = (const float*)d_in[13];
    const float* b_f2 = (const float*)d_in[14];
    const float* W_f3 = (const float*)d_in[15];
    const float* b_f3 = (const float*)d_in[16];

    float* x = (float*)d_out;

    float* y;
    __nv_bfloat16 *whi, *wlo;
    int *cnt, *cur, *rp, *partp;
    int2* cvp;
    cudaGetSymbolAddress((void**)&y,     g_y);
    cudaGetSymbolAddress((void**)&whi,   g_wt_hi);
    cudaGetSymbolAddress((void**)&wlo,   g_wt_lo);
    cudaGetSymbolAddress((void**)&cnt,   g_cnt);
    cudaGetSymbolAddress((void**)&cur,   g_cur);
    cudaGetSymbolAddress((void**)&rp,    g_rp);
    cudaGetSymbolAddress((void**)&partp, g_part);
    cudaGetSymbolAddress((void**)&cvp,   g_cv);

    cudaFuncSetAttribute(fused_mlp3, cudaFuncAttributeMaxDynamicSharedMemorySize, FUSED_SMEM);

    const int OH1 = 0, OH2 = 32768, OH3 = 98304, OF1 = 131072, OF2 = 163840, OF3 = 229376;

    // weight prep + CSR build (once per call)
    prep_all<<<262144 / 256, 256>>>(W_h1, W_h2, W_h3, W_f1, W_f2, W_f3, whi, wlo);
    zero_int<<<(DEPTH * NN + 255) / 256, 256>>>(cnt, DEPTH * NN);
    hist_kernel<<<(DEPTH * EE / 4 + 255) / 256, 256>>>(edge_src, cnt);
    part_kernel<<<DEPTH * NBLK, 512>>>(cnt, partp);
    scanp_kernel<<<DEPTH, 128>>>(partp);
    scan2_kernel<<<DEPTH * NBLK, 512>>>(cnt, partp, rp, cur);
    fill_kernel<<<(DEPTH * EE / 4 + 255) / 256, 256>>>(edge_src, edge_dst, adj_vals,
                                                       cur, cvp);

    const int GRID = (NN + 127) / 128;   // 391

    // embedding MLP: x = mlp3(node_inputs; W_h*)
    fused_mlp3<<<GRID, NTHREADS, FUSED_SMEM>>>(node_inputs,
        whi + OH1, wlo + OH1, whi + OH2, wlo + OH2, whi + OH3, wlo + OH3,
        b_h1, b_h2, b_h3, nullptr, nullptr, nullptr, x, nullptr, nullptr, NN);

    for (int d = 0; d < DEPTH; d++) {
        // y = mlp3(x)
        fused_mlp3<<<GRID, NTHREADS, FUSED_SMEM>>>(x,
            whi + OF1, wlo + OF1, whi + OF2, wlo + OF2, whi + OF3, wlo + OF3,
            b_f1, b_f2, b_f3, nullptr, nullptr, nullptr, y, nullptr, nullptr, NN);

        // x = x + mask[d] * mlp3(segment_sum(val*y[dst], src))  — gather fused in
        fused_mlp3<<<GRID, NTHREADS, FUSED_SMEM>>>(nullptr,
            whi + OF1, wlo + OF1, whi + OF2, wlo + OF2, whi + OF3, wlo + OF3,
            b_f1, b_f2, b_f3, rp + d * (NN + 1), cvp + (size_t)d * EE, y,
            x, x, masks + (size_t)d * NN, NN);
    }
}